// round 6
// baseline (speedup 1.0000x reference)
#include <cuda_runtime.h>
#include <math.h>

#define BB  512          // batch
#define TT  55           // timesteps
#define CC  512          // input width
#define DD  512          // hidden
#define KK  64           // key size
#define LL  3            // layers
#define OO  512          // output
#define BT  (BB*TT)      // 28160
#define BD  (BB*DD)      // 262144
#define G4  2048         // 4*D

// ---------------- device scratch (static globals; no allocation) ----------------
__device__ float g_gx[(size_t)LL*BT*G4];      // X @ wx_w[l][:C]  for all (b,t)
__device__ float g_Grx[(size_t)LL*BT*KK];     // X @ wr_w[l][:C]
__device__ float g_d0all[(size_t)BT*KK];      // layer-0 d state for all t (x-only scan)
__device__ float g_dd0[(size_t)BT*DD];        // d0all @ wd (raw; tanh applied in update)
__device__ float g_h[2*LL*BD];                // ping-pong h state
__device__ float g_c[LL*BD];
__device__ float g_d[LL*BB*KK];
__device__ float g_dd[BD];                    // tanh(d_new @ wd) for current layer (l>=1)
__device__ float g_part[12*(size_t)BB*G4];    // gate GEMM K-split partials (z<=12)
__device__ float g_ppart[12*(size_t)BB*OO];   // proj GEMM partials (z<=12)

struct Seg  { const float* A; long long lda; const float* Bw; long long ldb; int K; };
struct Segs { Seg s[12]; };

__device__ __forceinline__ float sigm(float x) { return 1.0f/(1.0f+expf(-x)); }

// ---- packed f32x2 FMA (ptxas won't emit from C++, PTX only) ----
__device__ __forceinline__ void fma2(unsigned long long &d, unsigned long long a, unsigned long long b){
    asm("fma.rn.f32x2 %0, %1, %2, %0;" : "+l"(d) : "l"(a), "l"(b));
}

// ---------------- segmented SGEMM: f32x2, dup-A SMEM, double-buffered ----------------
// BMxBN tile per block, BK=16, TM=TN=8, threads = (BM/8)*(BN/8).
// A tile stored DUPLICATED in smem: a_s[k][2m] = a_s[k][2m+1] = A[m][k], so LDS.128
// yields broadcast pairs directly (no MOV packing). Double-buffered, reg prefetch.
// Requires M%BM==0, N%BN==0, K%16==0. out += z*zstride for segment z = blockIdx.z.
template<int BM, int BN>
__global__ void __launch_bounds__((BM/8)*(BN/8), 2)
gemm2(Segs segs, float* __restrict__ out, long long ldc, long long zstride)
{
    constexpr int BK = 16, TM = 8, TN = 8;
    constexpr int TX = BN/TN, TY = BM/TM, NT = TX*TY;
    constexpr int ABUF = BK*2*BM;            // floats per A buffer (duplicated)
    constexpr int BBUF = BK*BN;
    constexpr int APF  = BM*BK/4/NT;         // float4 per thread (A tile)
    constexpr int BPF  = BK*BN/4/NT;         // float4 per thread (B tile)

    extern __shared__ float smem[];
    float* a_s = smem;                        // [2][ABUF]
    float* b_s = smem + 2*ABUF;               // [2][BBUF]

    const int tid  = threadIdx.x;
    const int tx   = tid % TX;
    const int ty   = tid / TX;
    const int row0 = blockIdx.y * BM;
    const int col0 = blockIdx.x * BN;
    const Seg sg   = segs.s[blockIdx.z];

    unsigned long long acc[TM][TN/2];
#pragma unroll
    for (int i = 0; i < TM; i++)
#pragma unroll
        for (int j = 0; j < TN/2; j++) acc[i][j] = 0ull;

    float4 pa[APF], pb[BPF];
    const int nk = sg.K / BK;

    auto ldg = [&](int kt) {
        const int k0 = kt * BK;
#pragma unroll
        for (int i = 0; i < APF; i++) {
            int e  = tid + i*NT;
            int r  = e / (BK/4);
            int kq = (e % (BK/4)) * 4;
            pa[i] = *(const float4*)(sg.A + (long long)(row0 + r)*sg.lda + k0 + kq);
        }
#pragma unroll
        for (int i = 0; i < BPF; i++) {
            int e  = tid + i*NT;
            int kk = e / (BN/4);
            int n4 = (e % (BN/4)) * 4;
            pb[i] = *(const float4*)(sg.Bw + (long long)(k0+kk)*sg.ldb + col0 + n4);
        }
    };
    auto sts = [&](int buf) {
        float* ab = a_s + buf*ABUF;
        float* bb = b_s + buf*BBUF;
#pragma unroll
        for (int i = 0; i < APF; i++) {
            int e  = tid + i*NT;
            int r  = e / (BK/4);
            int kq = (e % (BK/4)) * 4;
            *(float2*)&ab[(kq+0)*(2*BM) + 2*r] = make_float2(pa[i].x, pa[i].x);
            *(float2*)&ab[(kq+1)*(2*BM) + 2*r] = make_float2(pa[i].y, pa[i].y);
            *(float2*)&ab[(kq+2)*(2*BM) + 2*r] = make_float2(pa[i].z, pa[i].z);
            *(float2*)&ab[(kq+3)*(2*BM) + 2*r] = make_float2(pa[i].w, pa[i].w);
        }
#pragma unroll
        for (int i = 0; i < BPF; i++) {
            int e  = tid + i*NT;
            int kk = e / (BN/4);
            int n4 = (e % (BN/4)) * 4;
            *(float4*)&bb[kk*BN + n4] = pb[i];
        }
    };

    ldg(0); sts(0); __syncthreads();
    int cur = 0;
    for (int kt = 0; kt < nk; kt++) {
        if (kt + 1 < nk) ldg(kt + 1);
        const float* ap0 = a_s + cur*ABUF + 2*(ty*TM);
        const float* bp0 = b_s + cur*BBUF + tx*TN;
#pragma unroll
        for (int kk = 0; kk < BK; kk++) {
            unsigned long long aa[TM], bq[TN/2];
            const ulonglong2* ap = (const ulonglong2*)(ap0 + kk*(2*BM));
            const ulonglong2* bp = (const ulonglong2*)(bp0 + kk*BN);
#pragma unroll
            for (int i = 0; i < TM/2; i++) { ulonglong2 u = ap[i]; aa[2*i] = u.x; aa[2*i+1] = u.y; }
#pragma unroll
            for (int j = 0; j < TN/4; j++) { ulonglong2 v = bp[j]; bq[2*j] = v.x; bq[2*j+1] = v.y; }
#pragma unroll
            for (int i = 0; i < TM; i++)
#pragma unroll
                for (int j = 0; j < TN/2; j++)
                    fma2(acc[i][j], aa[i], bq[j]);
        }
        if (kt + 1 < nk) { sts(cur ^ 1); __syncthreads(); }
        cur ^= 1;
    }

    float* o = out + (long long)blockIdx.z * zstride;
#pragma unroll
    for (int i = 0; i < TM; i++) {
        long long r = row0 + ty*TM + i;
        float* orow = o + r*ldc + col0 + tx*TN;
#pragma unroll
        for (int j = 0; j < TN/2; j++)
            *(unsigned long long*)&orow[2*j] = acc[i][j];
    }
}

// ---------------- key-gate kernel (layers 1,2 only; per step) ----------------
__global__ void k1_kernel(int l, int t,
                          const float* __restrict__ hp, const float* __restrict__ hn,
                          const float* __restrict__ grx,
                          const float* __restrict__ wr_l,
                          const float* __restrict__ wl0, const float* __restrict__ wl1,
                          const float* __restrict__ wd,
                          float* __restrict__ dstate, float* __restrict__ dd)
{
    __shared__ float dn_s[4][KK];
    const int tid = threadIdx.x;        // 256
    const int r   = tid >> 6;           // 0..3
    const int kk  = tid & 63;
    const int b   = blockIdx.x*4 + r;

    float acc = grx[((long long)b*TT + t)*KK + kk];
    for (int j = 0; j < l; j++) {
        const float* hnj = hn + (size_t)j*BD + (size_t)b*DD;
        const float* hpj = hp + (size_t)j*BD + (size_t)b*DD;
        const float* wrp = wr_l + (size_t)(CC + j*DD)*KK + kk;
        const float* wlp = (j == 0 ? wl0 : wl1) + kk;
        float s0=0.f,s1=0.f,s2=0.f,s3=0.f;
        float u0=0.f,u1=0.f,u2=0.f,u3=0.f;
#pragma unroll 4
        for (int m = 0; m < DD; m += 4) {
            s0 = fmaf(hnj[m+0], wrp[(size_t)(m+0)*KK], s0);
            s1 = fmaf(hnj[m+1], wrp[(size_t)(m+1)*KK], s1);
            s2 = fmaf(hnj[m+2], wrp[(size_t)(m+2)*KK], s2);
            s3 = fmaf(hnj[m+3], wrp[(size_t)(m+3)*KK], s3);
            u0 = fmaf(hpj[m+0], wlp[(size_t)(m+0)*KK], u0);
            u1 = fmaf(hpj[m+1], wlp[(size_t)(m+1)*KK], u1);
            u2 = fmaf(hpj[m+2], wlp[(size_t)(m+2)*KK], u2);
            u3 = fmaf(hpj[m+3], wlp[(size_t)(m+3)*KK], u3);
        }
        acc += (s0+s1)+(s2+s3) + ((u0+u1)+(u2+u3)) * (1.0f/3.0f);
    }
    float rr = sigm(acc);
    float dn = rr * dstate[b*KK + kk];
    dstate[b*KK + kk] = dn;
    dn_s[r][kk] = dn;
    __syncthreads();

    for (int e = tid; e < 4*DD; e += 256) {
        int r2 = e >> 9;
        int n  = e & 511;
        int bb = blockIdx.x*4 + r2;
        float s = 0.0f;
#pragma unroll
        for (int q = 0; q < KK; q++)
            s = fmaf(dn_s[r2][q], wd[(size_t)q*DD + n], s);
        dd[(size_t)bb*DD + n] = tanhf(s);
    }
}

// ---------------- LSTM elementwise update (reduces K-split partials) ----------------
__global__ void lstm_update(int nparts, int t, int dd0mode,
                            const float* __restrict__ gx,
                            const float* __restrict__ wxb, const float* __restrict__ whb,
                            const float* __restrict__ part, const float* __restrict__ dd,
                            float* __restrict__ c, float* __restrict__ h)
{
    const long long idx = (long long)blockIdx.x*256 + threadIdx.x;   // < B*D
    const int b = (int)(idx >> 9);
    const int n = (int)(idx & 511);

    const float* gxr = gx + ((long long)b*TT + t)*G4;
    float g0 = gxr[n]        + wxb[n]        + whb[n];
    float g1 = gxr[DD+n]     + wxb[DD+n]     + whb[DD+n];
    float g2 = gxr[2*DD+n]   + wxb[2*DD+n]   + whb[2*DD+n];
    float g3 = gxr[3*DD+n]   + wxb[3*DD+n]   + whb[3*DD+n];
    const float* pp = part + (long long)b*G4;
    for (int z = 0; z < nparts; z++, pp += (long long)BB*G4) {
        g0 += pp[n]; g1 += pp[DD+n]; g2 += pp[2*DD+n]; g3 += pp[3*DD+n];
    }
    float f  = sigm(g0);
    float i  = sigm(g1);
    float o  = sigm(g2);
    float cb = tanhf(g3);
    float ddv = dd0mode ? tanhf(dd[((long long)b*TT + t)*DD + n]) : dd[idx];
    float cv = f*c[idx] + i*cb + ddv;
    c[idx] = cv;
    h[idx] = o * tanhf(cv);
}

// ---------------- layer-0 key scan: d0(t) = keys * prod sigm(Grx0) ----------------
__global__ void scan_d0(const float* __restrict__ grx0, const float* __restrict__ keys,
                        float* __restrict__ d0all)
{
    int i = blockIdx.x*256 + threadIdx.x;    // < B*K
    int b = i >> 6, kk = i & 63;
    float d = keys[i];
    for (int t = 0; t < TT; t++) {
        float g = grx0[((long long)b*TT + t)*KK + kk];
        d *= 1.0f/(1.0f + expf(-g));
        d0all[((long long)b*TT + t)*KK + kk] = d;
    }
}

// ---------------- projection output (reduce partials + bias) ----------------
__global__ void projout(int t, int nparts, const float* __restrict__ pb,
                        const float* __restrict__ pp, float* __restrict__ out)
{
    const long long idx = (long long)blockIdx.x*256 + threadIdx.x;   // < B*OUT
    const int b = (int)(idx >> 9);
    const int n = (int)(idx & 511);
    float v = pb[n];
    for (int z = 0; z < nparts; z++) v += pp[(long long)z*BB*OO + idx];
    out[((long long)b*TT + t)*OO + n] = v;
}

// ---------------- state init ----------------
__global__ void init_kernel(float* __restrict__ h, float* __restrict__ c,
                            float* __restrict__ d, const float* __restrict__ keys)
{
    for (long long idx = (long long)blockIdx.x*256 + threadIdx.x;
         idx < 2ll*LL*BD; idx += (long long)gridDim.x*256) {
        h[idx] = 0.0f;
        if (idx < (long long)LL*BD)    c[idx] = 0.0f;
        if (idx < (long long)LL*BB*KK) d[idx] = keys[idx % (BB*KK)];
    }
}

// ---------------- host orchestration ----------------
extern "C" void kernel_launch(void* const* d_in, const int* in_sizes, int n_in,
                              void* d_out, int out_size)
{
    const float* X    = (const float*)d_in[0];
    const float* keys = (const float*)d_in[1];

    const float *wx_w[LL], *wx_b[LL], *wh_w[LL], *wh_b[LL], *wr_w[LL], *wl_w[LL];
    if (in_sizes[4] == 512*2048) {
        for (int l = 0; l < LL; l++) {      // dict order
            int base = 2 + 6*l;
            wx_w[l] = (const float*)d_in[base+0];
            wx_b[l] = (const float*)d_in[base+1];
            wh_w[l] = (const float*)d_in[base+2];
            wh_b[l] = (const float*)d_in[base+3];
            wr_w[l] = (const float*)d_in[base+4];
            wl_w[l] = (const float*)d_in[base+5];
        }
    } else {
        for (int l = 0; l < LL; l++) {      // signature order
            wx_w[l] = (const float*)d_in[2 + 2*l];
            wx_b[l] = (const float*)d_in[3 + 2*l];
            wh_w[l] = (const float*)d_in[8 + 2*l];
            wh_b[l] = (const float*)d_in[9 + 2*l];
            wr_w[l] = (const float*)d_in[14 + l];
            wl_w[l] = (const float*)d_in[17 + l];
        }
    }
    const float* wd     = (const float*)d_in[20];
    const float* proj_w = (const float*)d_in[21];
    const float* proj_b = (const float*)d_in[22];
    float* out = (float*)d_out;

    float *p_gx, *p_Grx, *p_d0all, *p_dd0, *p_h, *p_c, *p_d, *p_dd, *p_part, *p_ppart;
    cudaGetSymbolAddress((void**)&p_gx,    g_gx);
    cudaGetSymbolAddress((void**)&p_Grx,   g_Grx);
    cudaGetSymbolAddress((void**)&p_d0all, g_d0all);
    cudaGetSymbolAddress((void**)&p_dd0,   g_dd0);
    cudaGetSymbolAddress((void**)&p_h,     g_h);
    cudaGetSymbolAddress((void**)&p_c,     g_c);
    cudaGetSymbolAddress((void**)&p_d,     g_d);
    cudaGetSymbolAddress((void**)&p_dd,    g_dd);
    cudaGetSymbolAddress((void**)&p_part,  g_part);
    cudaGetSymbolAddress((void**)&p_ppart, g_ppart);

    const int S128 = (2*16*2*128 + 2*16*128) * 4;   // 49152 B
    const int S64  = (2*16*2*128 + 2*16*64)  * 4;   // 40960 B
    cudaFuncSetAttribute(gemm2<128,128>, cudaFuncAttributeMaxDynamicSharedMemorySize, S128);
    cudaFuncSetAttribute(gemm2<128,64>,  cudaFuncAttributeMaxDynamicSharedMemorySize, S64);

    // reset recurrent state
    init_kernel<<<6144, 256>>>(p_h, p_c, p_d, keys);

    // Grx_l = X @ wr_w[l][:C] for all (b,t)   (N=64, z=3)
    {
        Segs sg{};
        for (int l = 0; l < LL; l++)
            sg.s[l] = { X, (long long)CC, wr_w[l], (long long)KK, 512 };
        dim3 g(1, BT/128, 3);
        gemm2<128,64><<<g, 128, S64>>>(sg, p_Grx, KK, (long long)BT*KK);
    }

    // layer-0 key path is x-only: scan d0 over t, then dd0 = d0all @ wd (raw)
    scan_d0<<<BB*KK/256, 256>>>(p_Grx, keys, p_d0all);
    {
        Segs sg{};
        sg.s[0] = { p_d0all, (long long)KK, wd, (long long)DD, KK };
        dim3 g(DD/128, BT/128, 1);
        gemm2<128,128><<<g, 256, S128>>>(sg, p_dd0, DD, 0);
    }

    // Gx_l = X @ wx_w[l][:C] for all (b,t)   (big parallel GEMM, z=3)
    {
        Segs sg{};
        for (int l = 0; l < LL; l++)
            sg.s[l] = { X, (long long)CC, wx_w[l], (long long)G4, 512 };
        dim3 g(G4/128, BT/128, 3);
        gemm2<128,128><<<g, 256, S128>>>(sg, p_gx, G4, (long long)BT*G4);
    }

    const int KCH = 128;   // K chunk for serial-phase split-K
    for (int t = 0; t < TT; t++) {
        int par = t & 1;
        float* hp = p_h + (long long)par     * LL * BD;
        float* hn = p_h + (long long)(1-par) * LL * BD;

        for (int l = 0; l < LL; l++) {
            if (l > 0) {
                k1_kernel<<<BB/4, 256>>>(l, t, hp, hn,
                                         p_Grx + (long long)l*BT*KK,
                                         wr_w[l], wl_w[0], wl_w[1], wd,
                                         p_d + (long long)l*BB*KK, p_dd);
            }

            // gate GEMM over h segments only, K split into 128-chunks
            Segs sg{};
            int ns = 0;
            for (int kc = 0; kc < DD; kc += KCH)
                sg.s[ns++] = { hp + (long long)l*BD + kc, (long long)DD,
                               wh_w[l] + (long long)kc*G4, (long long)G4, KCH };
            for (int j = 0; j < l; j++)
                for (int kc = 0; kc < DD; kc += KCH)
                    sg.s[ns++] = { hn + (long long)j*BD + kc, (long long)DD,
                                   wx_w[l] + (long long)(CC + j*DD + kc)*G4,
                                   (long long)G4, KCH };
            dim3 gg(G4/128, BB/128, ns);
            gemm2<128,128><<<gg, 256, S128>>>(sg, p_part, G4, (long long)BB*G4);

            lstm_update<<<BD/256, 256>>>(ns, t, (l == 0) ? 1 : 0,
                                         p_gx + (long long)l*BT*G4,
                                         wx_b[l], wh_b[l], p_part,
                                         (l == 0) ? p_dd0 : p_dd,
                                         p_c + (long long)l*BD,
                                         hn + (long long)l*BD);
        }

        // projection: out_t = concat(h) @ proj_w + proj_b   (z = 12 K-chunks)
        {
            Segs ps{};
            int ns = 0;
            for (int l = 0; l < LL; l++)
                for (int kc = 0; kc < DD; kc += KCH)
                    ps.s[ns++] = { hn + (long long)l*BD + kc, (long long)DD,
                                   proj_w + (long long)(l*DD + kc)*OO,
                                   (long long)OO, KCH };
            dim3 pg(OO/128, BB/128, ns);
            gemm2<128,128><<<pg, 256, S128>>>(ps, p_ppart, OO, (long long)BB*OO);
            projout<<<BB*OO/256, 256>>>(t, ns, proj_b, p_ppart, out);
        }
    }
}

// round 8
// speedup vs baseline: 1.5228x; 1.5228x over previous
#include <cuda_runtime.h>
#include <math.h>

#define BB  512          // batch
#define TT  55           // timesteps
#define CC  512          // input width
#define DD  512          // hidden
#define KK  64           // key size
#define LL  3            // layers
#define OO  512          // output
#define BT  (BB*TT)      // 28160
#define BD  (BB*DD)      // 262144
#define G4  2048         // 4*D

// ---------------- device scratch (static globals; no allocation) ----------------
__device__ float g_gx[(size_t)LL*BT*G4];      // X @ wx_w[l][:C]  for all (b,t)
__device__ float g_Grx[(size_t)LL*BT*KK];     // X @ wr_w[l][:C]
__device__ float g_d0all[(size_t)BT*KK];      // layer-0 d state for all t (x-only scan)
__device__ float g_dd0[(size_t)BT*DD];        // d0all @ wd (raw; tanh applied in update)
__device__ float g_h[2*LL*BD];                // ping-pong h state
__device__ float g_c[LL*BD];
__device__ float g_d[LL*BB*KK];
__device__ float g_dd[BD];                    // tanh(d_new @ wd) for current layer (l>=1)
__device__ float g_part[12*(size_t)BB*G4];    // gate GEMM K-split partials
__device__ float g_ppart[12*(size_t)BB*OO];   // proj GEMM partials

struct Seg  { const float* A; long long lda; const float* Bw; long long ldb; int K; };
struct Segs { Seg s[12]; };

// args for the fused key-gate plane (z == k1z)
struct K1A {
    const float *hp, *hn, *grx, *wr, *wl0, *wl1, *wd;
    float *dst, *dd;
    int l, t;
};

__device__ __forceinline__ float sigm(float x) { return 1.0f/(1.0f+expf(-x)); }

// ---- packed f32x2 FMA (ptxas won't emit from C++, PTX only) ----
__device__ __forceinline__ void fma2(unsigned long long &d, unsigned long long a, unsigned long long b){
    asm("fma.rn.f32x2 %0, %1, %2, %0;" : "+l"(d) : "l"(a), "l"(b));
}

// ---------------- fused key-gate body (runs on z==k1z plane; 128 threads) ----------------
// gr = Grx + sum_{j<l} hnew_j @ wr_l[rows C+jD..] + (1/3) sum_{j<l} hprev_j @ wl_j
// r = sigmoid(gr); d = r*d;  dd = tanh(d @ wd)
__device__ void k1_body(const K1A& a, int bx)
{
    __shared__ float dn_s[4][KK];
    const int tid = threadIdx.x;        // 128
    const int r   = tid >> 5;           // 0..3 (batch row within block)
    const int q   = tid & 31;           // handles kk = q and q+32
    const int b   = bx*4 + r;

    const long long gro = ((long long)b*TT + a.t)*KK;
    float acc0 = a.grx[gro + q];
    float acc1 = a.grx[gro + q + 32];
    for (int j = 0; j < a.l; j++) {
        const float* hnj = a.hn + (size_t)j*BD + (size_t)b*DD;
        const float* hpj = a.hp + (size_t)j*BD + (size_t)b*DD;
        const float* wrp = a.wr + (size_t)(CC + j*DD)*KK;
        const float* wlp = (j == 0 ? a.wl0 : a.wl1);
        float u0 = 0.f, u1 = 0.f;
#pragma unroll 4
        for (int m = 0; m < DD; m++) {
            float hv = hnj[m], pv = hpj[m];
            acc0 = fmaf(hv, wrp[(size_t)m*KK + q],      acc0);
            acc1 = fmaf(hv, wrp[(size_t)m*KK + q + 32], acc1);
            u0   = fmaf(pv, wlp[(size_t)m*KK + q],      u0);
            u1   = fmaf(pv, wlp[(size_t)m*KK + q + 32], u1);
        }
        acc0 += u0 * (1.0f/3.0f);
        acc1 += u1 * (1.0f/3.0f);
    }
    float dn0 = sigm(acc0) * a.dst[b*KK + q];
    float dn1 = sigm(acc1) * a.dst[b*KK + q + 32];
    a.dst[b*KK + q]      = dn0;
    a.dst[b*KK + q + 32] = dn1;
    dn_s[r][q]      = dn0;
    dn_s[r][q + 32] = dn1;
    __syncthreads();

    // dd = tanh(d_new @ wd), 4 rows x 512 cols per block
    for (int e = tid; e < 4*DD; e += 128) {
        int r2 = e >> 9;
        int n  = e & 511;
        int bb = bx*4 + r2;
        float s = 0.0f;
#pragma unroll
        for (int qq = 0; qq < KK; qq++)
            s = fmaf(dn_s[r2][qq], a.wd[(size_t)qq*DD + n], s);
        a.dd[(size_t)bb*DD + n] = tanhf(s);
    }
}

// ---------------- segmented SGEMM: f32x2 with duplicated-A SMEM ----------------
// BM=64 fixed, BK=16, single-buffered (measured-good baseline structure).
// A stored duplicated: a_s[k][2m]=a_s[k][2m+1]=A[m][k] (+8 pad kills bank alignment),
// so LDS.128 yields broadcast pairs and B pairs load directly as u64 -> zero pack MOVs.
// z = blockIdx.z selects segment; if z == k1z the block runs the key-gate body instead.
// Requires M%64==0, N%BN==0, K%16==0.
template<int BN, int TM, int TN>
__global__ void __launch_bounds__((BN/TN)*(64/TM))
gemm2(Segs segs, K1A ka, int k1z,
      float* __restrict__ out, long long ldc, long long zstride)
{
    constexpr int BM = 64, BK = 16;
    constexpr int TX = BN/TN, TY = BM/TM, NT = TX*TY;
    constexpr int AW = 2*BM + 8;               // padded dup-A row (floats)
    __shared__ __align__(16) float a_s[BK][AW];
    __shared__ __align__(16) float b_s[BK][BN];

    if ((int)blockIdx.z == k1z) {
        k1_body(ka, blockIdx.y * gridDim.x + blockIdx.x);
        return;
    }

    const int tid  = threadIdx.x;
    const int tx   = tid % TX;
    const int ty   = tid / TX;
    const int row0 = blockIdx.y * BM;
    const int col0 = blockIdx.x * BN;
    const Seg sg   = segs.s[blockIdx.z];

    unsigned long long acc[TM][TN/2];
#pragma unroll
    for (int i = 0; i < TM; i++)
#pragma unroll
        for (int j = 0; j < TN/2; j++) acc[i][j] = 0ull;

    for (int k0 = 0; k0 < sg.K; k0 += BK) {
        // A tile [BM x BK] -> duplicated transposed a_s[k][2m],[2m+1]
#pragma unroll
        for (int e = tid; e < BM*BK/4; e += NT) {
            int r  = e >> 2;            // 0..63
            int kq = (e & 3) << 2;      // 0,4,8,12
            float4 v = *(const float4*)(sg.A + (long long)(row0 + r)*sg.lda + k0 + kq);
            *(float2*)&a_s[kq+0][2*r] = make_float2(v.x, v.x);
            *(float2*)&a_s[kq+1][2*r] = make_float2(v.y, v.y);
            *(float2*)&a_s[kq+2][2*r] = make_float2(v.z, v.z);
            *(float2*)&a_s[kq+3][2*r] = make_float2(v.w, v.w);
        }
        // B tile [BK x BN]
#pragma unroll
        for (int e = tid; e < BK*BN/4; e += NT) {
            int kk = e / (BN/4);
            int n4 = (e % (BN/4)) * 4;
            *(float4*)&b_s[kk][n4] =
                *(const float4*)(sg.Bw + (long long)(k0+kk)*sg.ldb + col0 + n4);
        }
        __syncthreads();
#pragma unroll
        for (int kk = 0; kk < BK; kk++) {
            unsigned long long aa[TM], bq[TN/2];
            const ulonglong2* ap = (const ulonglong2*)&a_s[kk][2*(ty*TM)];
            const ulonglong2* bp = (const ulonglong2*)&b_s[kk][tx*TN];
#pragma unroll
            for (int i = 0; i < TM/2; i++) { ulonglong2 u = ap[i]; aa[2*i] = u.x; aa[2*i+1] = u.y; }
#pragma unroll
            for (int j = 0; j < TN/4; j++) { ulonglong2 v = bp[j]; bq[2*j] = v.x; bq[2*j+1] = v.y; }
#pragma unroll
            for (int i = 0; i < TM; i++)
#pragma unroll
                for (int j = 0; j < TN/2; j++)
                    fma2(acc[i][j], aa[i], bq[j]);
        }
        __syncthreads();
    }

    float* o = out + (long long)blockIdx.z * zstride;
#pragma unroll
    for (int i = 0; i < TM; i++) {
        long long r = row0 + ty*TM + i;
        float* orow = o + r*ldc + col0 + tx*TN;
#pragma unroll
        for (int j = 0; j < TN/2; j++)
            *(unsigned long long*)&orow[2*j] = acc[i][j];
    }
}

// ---------------- LSTM elementwise update (reduces K-split partials) ----------------
__global__ void lstm_update(int nparts, int t, int dd0mode,
                            const float* __restrict__ gx,
                            const float* __restrict__ wxb, const float* __restrict__ whb,
                            const float* __restrict__ part, const float* __restrict__ dd,
                            float* __restrict__ c, float* __restrict__ h)
{
    const long long idx = (long long)blockIdx.x*256 + threadIdx.x;   // < B*D
    const int b = (int)(idx >> 9);
    const int n = (int)(idx & 511);

    const float* gxr = gx + ((long long)b*TT + t)*G4;
    float g0 = gxr[n]        + wxb[n]        + whb[n];
    float g1 = gxr[DD+n]     + wxb[DD+n]     + whb[DD+n];
    float g2 = gxr[2*DD+n]   + wxb[2*DD+n]   + whb[2*DD+n];
    float g3 = gxr[3*DD+n]   + wxb[3*DD+n]   + whb[3*DD+n];
    const float* pp = part + (long long)b*G4;
    for (int z = 0; z < nparts; z++, pp += (long long)BB*G4) {
        g0 += pp[n]; g1 += pp[DD+n]; g2 += pp[2*DD+n]; g3 += pp[3*DD+n];
    }
    float f  = sigm(g0);
    float i  = sigm(g1);
    float o  = sigm(g2);
    float cb = tanhf(g3);
    float ddv = dd0mode ? tanhf(dd[((long long)b*TT + t)*DD + n]) : dd[idx];
    float cv = f*c[idx] + i*cb + ddv;
    c[idx] = cv;
    h[idx] = o * tanhf(cv);
}

// ---------------- layer-0 key scan: d0(t) = keys * prod sigm(Grx0) ----------------
__global__ void scan_d0(const float* __restrict__ grx0, const float* __restrict__ keys,
                        float* __restrict__ d0all)
{
    int i = blockIdx.x*256 + threadIdx.x;    // < B*K
    int b = i >> 6, kk = i & 63;
    float d = keys[i];
    for (int t = 0; t < TT; t++) {
        float g = grx0[((long long)b*TT + t)*KK + kk];
        d *= 1.0f/(1.0f + expf(-g));
        d0all[((long long)b*TT + t)*KK + kk] = d;
    }
}

// ---------------- projection output (reduce partials + bias) ----------------
__global__ void projout(int t, int nparts, const float* __restrict__ pb,
                        const float* __restrict__ pp, float* __restrict__ out)
{
    const long long idx = (long long)blockIdx.x*256 + threadIdx.x;   // < B*OUT
    const int b = (int)(idx >> 9);
    const int n = (int)(idx & 511);
    float v = pb[n];
    for (int z = 0; z < nparts; z++) v += pp[(long long)z*BB*OO + idx];
    out[((long long)b*TT + t)*OO + n] = v;
}

// ---------------- state init ----------------
__global__ void init_kernel(float* __restrict__ h, float* __restrict__ c,
                            float* __restrict__ d, const float* __restrict__ keys)
{
    for (long long idx = (long long)blockIdx.x*256 + threadIdx.x;
         idx < 2ll*LL*BD; idx += (long long)gridDim.x*256) {
        h[idx] = 0.0f;
        if (idx < (long long)LL*BD)    c[idx] = 0.0f;
        if (idx < (long long)LL*BB*KK) d[idx] = keys[idx % (BB*KK)];
    }
}

// ---------------- host orchestration ----------------
extern "C" void kernel_launch(void* const* d_in, const int* in_sizes, int n_in,
                              void* d_out, int out_size)
{
    const float* X    = (const float*)d_in[0];
    const float* keys = (const float*)d_in[1];

    const float *wx_w[LL], *wx_b[LL], *wh_w[LL], *wh_b[LL], *wr_w[LL], *wl_w[LL];
    if (in_sizes[4] == 512*2048) {
        for (int l = 0; l < LL; l++) {      // dict order
            int base = 2 + 6*l;
            wx_w[l] = (const float*)d_in[base+0];
            wx_b[l] = (const float*)d_in[base+1];
            wh_w[l] = (const float*)d_in[base+2];
            wh_b[l] = (const float*)d_in[base+3];
            wr_w[l] = (const float*)d_in[base+4];
            wl_w[l] = (const float*)d_in[base+5];
        }
    } else {
        for (int l = 0; l < LL; l++) {      // signature order
            wx_w[l] = (const float*)d_in[2 + 2*l];
            wx_b[l] = (const float*)d_in[3 + 2*l];
            wh_w[l] = (const float*)d_in[8 + 2*l];
            wh_b[l] = (const float*)d_in[9 + 2*l];
            wr_w[l] = (const float*)d_in[14 + l];
            wl_w[l] = (const float*)d_in[17 + l];
        }
    }
    const float* wd     = (const float*)d_in[20];
    const float* proj_w = (const float*)d_in[21];
    const float* proj_b = (const float*)d_in[22];
    float* out = (float*)d_out;

    float *p_gx, *p_Grx, *p_d0all, *p_dd0, *p_h, *p_c, *p_d, *p_dd, *p_part, *p_ppart;
    cudaGetSymbolAddress((void**)&p_gx,    g_gx);
    cudaGetSymbolAddress((void**)&p_Grx,   g_Grx);
    cudaGetSymbolAddress((void**)&p_d0all, g_d0all);
    cudaGetSymbolAddress((void**)&p_dd0,   g_dd0);
    cudaGetSymbolAddress((void**)&p_h,     g_h);
    cudaGetSymbolAddress((void**)&p_c,     g_c);
    cudaGetSymbolAddress((void**)&p_d,     g_d);
    cudaGetSymbolAddress((void**)&p_dd,    g_dd);
    cudaGetSymbolAddress((void**)&p_part,  g_part);
    cudaGetSymbolAddress((void**)&p_ppart, g_ppart);

    K1A nok1{};   // unused plane args (k1z = -1)

    // reset recurrent state
    init_kernel<<<6144, 256>>>(p_h, p_c, p_d, keys);

    // Grx_l = X @ wr_w[l][:C] for all (b,t)   (N=64, z=3)
    {
        Segs sg{};
        for (int l = 0; l < LL; l++)
            sg.s[l] = { X, (long long)CC, wr_w[l], (long long)KK, 512 };
        dim3 g(1, BT/64, 3);
        gemm2<64,4,8><<<g, 128>>>(sg, nok1, -1, p_Grx, KK, (long long)BT*KK);
    }

    // layer-0 key path is x-only: scan d0 over t, then dd0 = d0all @ wd (raw)
    scan_d0<<<BB*KK/256, 256>>>(p_Grx, keys, p_d0all);
    {
        Segs sg{};
        sg.s[0] = { p_d0all, (long long)KK, wd, (long long)DD, KK };
        dim3 g(DD/128, BT/64, 1);
        gemm2<128,8,8><<<g, 128>>>(sg, nok1, -1, p_dd0, DD, 0);
    }

    // Gx_l = X @ wx_w[l][:C] for all (b,t)   (big parallel GEMM, z=3)
    {
        Segs sg{};
        for (int l = 0; l < LL; l++)
            sg.s[l] = { X, (long long)CC, wx_w[l], (long long)G4, 512 };
        dim3 g(G4/128, BT/64, 3);
        gemm2<128,8,8><<<g, 128>>>(sg, nok1, -1, p_gx, G4, (long long)BT*G4);
    }

    const int KCH = 256;   // K chunk for serial-phase split-K (baseline-proven)
    for (int t = 0; t < TT; t++) {
        int par = t & 1;
        float* hp = p_h + (long long)par     * LL * BD;
        float* hn = p_h + (long long)(1-par) * LL * BD;

        for (int l = 0; l < LL; l++) {
            // gate GEMM over h segments, K split into 256-chunks;
            // for l>0 an extra z-plane runs the key-gate (k1) concurrently.
            Segs sg{};
            int ns = 0;
            for (int kc = 0; kc < DD; kc += KCH)
                sg.s[ns++] = { hp + (long long)l*BD + kc, (long long)DD,
                               wh_w[l] + (long long)kc*G4, (long long)G4, KCH };
            for (int j = 0; j < l; j++)
                for (int kc = 0; kc < DD; kc += KCH)
                    sg.s[ns++] = { hn + (long long)j*BD + kc, (long long)DD,
                                   wx_w[l] + (long long)(CC + j*DD + kc)*G4,
                                   (long long)G4, KCH };
            int k1z = (l > 0) ? ns : -1;
            K1A ka{};
            if (l > 0) {
                ka.hp = hp; ka.hn = hn;
                ka.grx = p_Grx + (long long)l*BT*KK;
                ka.wr = wr_w[l]; ka.wl0 = wl_w[0]; ka.wl1 = wl_w[1]; ka.wd = wd;
                ka.dst = p_d + (long long)l*BB*KK; ka.dd = p_dd;
                ka.l = l; ka.t = t;
            }
            dim3 gg(G4/128, BB/64, ns + (l > 0 ? 1 : 0));
            gemm2<128,8,8><<<gg, 128>>>(sg, ka, k1z, p_part, G4, (long long)BB*G4);

            lstm_update<<<BD/256, 256>>>(ns, t, (l == 0) ? 1 : 0,
                                         p_gx + (long long)l*BT*G4,
                                         wx_b[l], wh_b[l], p_part,
                                         (l == 0) ? p_dd0 : p_dd,
                                         p_c + (long long)l*BD,
                                         hn + (long long)l*BD);
        }

        // projection: out_t = concat(h) @ proj_w + proj_b   (z = 6 K-chunks)
        {
            Segs ps{};
            int ns = 0;
            for (int l = 0; l < LL; l++)
                for (int kc = 0; kc < DD; kc += KCH)
                    ps.s[ns++] = { hn + (long long)l*BD + kc, (long long)DD,
                                   proj_w + (long long)(l*DD + kc)*OO,
                                   (long long)OO, KCH };
            dim3 pg(OO/64, BB/64, ns);
            gemm2<64,4,8><<<pg, 128>>>(ps, nok1, -1, p_ppart, OO, (long long)BB*OO);
            projout<<<BB*OO/256, 256>>>(t, ns, proj_b, p_ppart, out);
        }
    }
}

// round 9
// speedup vs baseline: 1.8256x; 1.1988x over previous
#include <cuda_runtime.h>
#include <math.h>

#define BB  512          // batch
#define TT  55           // timesteps
#define CC  512          // input width
#define DD  512          // hidden
#define KK  64           // key size
#define LL  3            // layers
#define OO  512          // output
#define BT  (BB*TT)      // 28160
#define BD  (BB*DD)      // 262144
#define G4  2048         // 4*D

// ---------------- device scratch (static globals; no allocation) ----------------
__device__ float g_gx[(size_t)LL*BT*G4];      // X @ wx_w[l][:C]  for all (b,t)
__device__ float g_Grx[(size_t)LL*BT*KK];     // X @ wr_w[l][:C]
__device__ float g_d0all[(size_t)BT*KK];      // layer-0 d state for all t (x-only scan)
__device__ float g_dd0[(size_t)BT*DD];        // d0all @ wd (raw; tanh applied in update)
__device__ float g_h[4*LL*BD];                // 4-slot ring: h_l(t) at ((t&3)*LL+l)*BD
__device__ float g_c[LL*BD];
__device__ float g_d[LL*BB*KK];
__device__ float g_dd[2*BD];                  // tanh(d@wd) for l=1 (slot0), l=2 (slot1)
__device__ float g_part[6*(size_t)BB*G4];     // gate GEMM outputs (6 planes)
__device__ float g_ppart[3*(size_t)BB*OO];    // proj GEMM outputs (3 planes)

// args for a fused key-gate plane
struct K1A {
    const float *hp, *hn, *grx, *wr, *wl0, *wl1, *wd;
    float *dst, *dd;
    int l, t;
};

// one GEMM plane (kind 0) or k1 plane (kind 1/2) or idle (kind -1)
struct Plane {
    const float* A; long long lda;
    const float* Bw; long long ldb;
    float* out; long long ldc;
    int K; int xmax; int kind;
};
struct StageArgs { Plane p[11]; K1A k1[2]; };

__device__ __forceinline__ float sigm(float x) { return 1.0f/(1.0f+expf(-x)); }

// ---- packed f32x2 FMA (ptxas won't emit from C++, PTX only) ----
__device__ __forceinline__ void fma2(unsigned long long &d, unsigned long long a, unsigned long long b){
    asm("fma.rn.f32x2 %0, %1, %2, %0;" : "+l"(d) : "l"(a), "l"(b));
}

// ---------------- fused key-gate body (128 threads) ----------------
// gr = Grx + sum_{j<l} h_j(t) @ wr_l[rows C+jD..] + (1/3) sum_{j<l} h_j(t-1) @ wl_j
// r = sigmoid(gr); d = r*d;  dd = tanh(d @ wd)
__device__ void k1_body(const K1A& a, int bx)
{
    __shared__ float dn_s[4][KK];
    const int tid = threadIdx.x;        // 128
    const int r   = tid >> 5;           // 0..3 (batch row within block)
    const int q   = tid & 31;           // handles kk = q and q+32
    const int b   = bx*4 + r;

    const long long gro = ((long long)b*TT + a.t)*KK;
    float acc0 = a.grx[gro + q];
    float acc1 = a.grx[gro + q + 32];
    for (int j = 0; j < a.l; j++) {
        const float* hnj = a.hn + (size_t)j*BD + (size_t)b*DD;
        const float* hpj = a.hp + (size_t)j*BD + (size_t)b*DD;
        const float* wrp = a.wr + (size_t)(CC + j*DD)*KK;
        const float* wlp = (j == 0 ? a.wl0 : a.wl1);
        float u0 = 0.f, u1 = 0.f;
#pragma unroll 4
        for (int m = 0; m < DD; m++) {
            float hv = hnj[m], pv = hpj[m];
            acc0 = fmaf(hv, wrp[(size_t)m*KK + q],      acc0);
            acc1 = fmaf(hv, wrp[(size_t)m*KK + q + 32], acc1);
            u0   = fmaf(pv, wlp[(size_t)m*KK + q],      u0);
            u1   = fmaf(pv, wlp[(size_t)m*KK + q + 32], u1);
        }
        acc0 += u0 * (1.0f/3.0f);
        acc1 += u1 * (1.0f/3.0f);
    }
    float dn0 = sigm(acc0) * a.dst[b*KK + q];
    float dn1 = sigm(acc1) * a.dst[b*KK + q + 32];
    a.dst[b*KK + q]      = dn0;
    a.dst[b*KK + q + 32] = dn1;
    dn_s[r][q]      = dn0;
    dn_s[r][q + 32] = dn1;
    __syncthreads();

    for (int e = tid; e < 4*DD; e += 128) {
        int r2 = e >> 9;
        int n  = e & 511;
        int bb = bx*4 + r2;
        float s = 0.0f;
#pragma unroll
        for (int qq = 0; qq < KK; qq++)
            s = fmaf(dn_s[r2][qq], a.wd[(size_t)qq*DD + n], s);
        a.dd[(size_t)bb*DD + n] = tanhf(s);
    }
}

// ---------------- multi-plane SGEMM: f32x2 with padded duplicated-A SMEM ----------------
// BM=64, BK=16, single-buffered (R8-proven). z = blockIdx.z selects plane:
// kind 0 -> GEMM (blocks with x>=xmax exit; supports N<BN*gridx planes),
// kind 1/2 -> key-gate body, kind -1 -> idle.
template<int BN, int TM, int TN>
__global__ void __launch_bounds__((BN/TN)*(64/TM))
gemm_stage(StageArgs SA)
{
    constexpr int BM = 64, BK = 16;
    constexpr int TX = BN/TN, TY = BM/TM, NT = TX*TY;
    constexpr int AW = 2*BM + 8;               // padded dup-A row (floats)
    __shared__ __align__(16) float a_s[BK][AW];
    __shared__ __align__(16) float b_s[BK][BN];

    const Plane pl = SA.p[blockIdx.z];
    if (pl.kind < 0) return;
    if (pl.kind > 0) {
        k1_body(SA.k1[pl.kind - 1], blockIdx.y * gridDim.x + blockIdx.x);
        return;
    }
    if ((int)blockIdx.x >= pl.xmax) return;

    const int tid  = threadIdx.x;
    const int tx   = tid % TX;
    const int ty   = tid / TX;
    const int row0 = blockIdx.y * BM;
    const int col0 = blockIdx.x * BN;

    unsigned long long acc[TM][TN/2];
#pragma unroll
    for (int i = 0; i < TM; i++)
#pragma unroll
        for (int j = 0; j < TN/2; j++) acc[i][j] = 0ull;

    for (int k0 = 0; k0 < pl.K; k0 += BK) {
        // A tile [BM x BK] -> duplicated transposed a_s[k][2m],[2m+1]
#pragma unroll
        for (int e = tid; e < BM*BK/4; e += NT) {
            int r  = e >> 2;            // 0..63
            int kq = (e & 3) << 2;      // 0,4,8,12
            float4 v = *(const float4*)(pl.A + (long long)(row0 + r)*pl.lda + k0 + kq);
            *(float2*)&a_s[kq+0][2*r] = make_float2(v.x, v.x);
            *(float2*)&a_s[kq+1][2*r] = make_float2(v.y, v.y);
            *(float2*)&a_s[kq+2][2*r] = make_float2(v.z, v.z);
            *(float2*)&a_s[kq+3][2*r] = make_float2(v.w, v.w);
        }
        // B tile [BK x BN]
#pragma unroll
        for (int e = tid; e < BK*BN/4; e += NT) {
            int kk = e / (BN/4);
            int n4 = (e % (BN/4)) * 4;
            *(float4*)&b_s[kk][n4] =
                *(const float4*)(pl.Bw + (long long)(k0+kk)*pl.ldb + col0 + n4);
        }
        __syncthreads();
#pragma unroll
        for (int kk = 0; kk < BK; kk++) {
            unsigned long long aa[TM], bq[TN/2];
            const ulonglong2* ap = (const ulonglong2*)&a_s[kk][2*(ty*TM)];
            const ulonglong2* bp = (const ulonglong2*)&b_s[kk][tx*TN];
#pragma unroll
            for (int i = 0; i < TM/2; i++) { ulonglong2 u = ap[i]; aa[2*i] = u.x; aa[2*i+1] = u.y; }
#pragma unroll
            for (int j = 0; j < TN/4; j++) { ulonglong2 v = bp[j]; bq[2*j] = v.x; bq[2*j+1] = v.y; }
#pragma unroll
            for (int i = 0; i < TM; i++)
#pragma unroll
                for (int j = 0; j < TN/2; j++)
                    fma2(acc[i][j], aa[i], bq[j]);
        }
        __syncthreads();
    }

#pragma unroll
    for (int i = 0; i < TM; i++) {
        long long r = row0 + ty*TM + i;
        float* orow = pl.out + r*pl.ldc + col0 + tx*TN;
#pragma unroll
        for (int j = 0; j < TN/2; j++)
            *(unsigned long long*)&orow[2*j] = acc[i][j];
    }
}

// ---------------- combined stage update: upd0/upd1/upd2 + projout ----------------
struct UpdA {
    int valid0, valid1, valid2, pvalid;
    int t0, t1, t2, tp;
    const float *gx0, *gx1, *gx2;
    const float *wxb0, *wxb1, *wxb2, *whb0, *whb1, *whb2;
    const float *part;       // p_part base (plane regions: l0 -> 0; l1 -> 1,2; l2 -> 3,4,5)
    const float *dd0;        // g_dd0 (t-indexed raw; tanh here)
    const float *dd;         // g_dd (2*BD)
    float *h;                // p_h base (4-slot ring)
    float *c;                // p_c base
    const float *pb; const float *pp; float *out;
};

__global__ void stage_update(UpdA u)
{
    const int rg = blockIdx.x >> 10;                 // 0..3
    const long long idx = ((long long)(blockIdx.x & 1023))*256 + threadIdx.x;  // < BD
    const int b = (int)(idx >> 9);
    const int n = (int)(idx & 511);

    if (rg < 3) {
        int valid = rg==0 ? u.valid0 : (rg==1 ? u.valid1 : u.valid2);
        if (!valid) return;
        int t = rg==0 ? u.t0 : (rg==1 ? u.t1 : u.t2);
        const float* gx  = rg==0 ? u.gx0  : (rg==1 ? u.gx1  : u.gx2);
        const float* wxb = rg==0 ? u.wxb0 : (rg==1 ? u.wxb1 : u.wxb2);
        const float* whb = rg==0 ? u.whb0 : (rg==1 ? u.whb1 : u.whb2);
        int pbase = rg==0 ? 0 : (rg==1 ? 1 : 3);
        int np    = rg + 1;

        const float* gxr = gx + ((long long)b*TT + t)*G4;
        float g0 = gxr[n]        + wxb[n]        + whb[n];
        float g1 = gxr[DD+n]     + wxb[DD+n]     + whb[DD+n];
        float g2 = gxr[2*DD+n]   + wxb[2*DD+n]   + whb[2*DD+n];
        float g3 = gxr[3*DD+n]   + wxb[3*DD+n]   + whb[3*DD+n];
        const float* pp = u.part + (long long)pbase*BB*G4 + (long long)b*G4;
        for (int z = 0; z < np; z++, pp += (long long)BB*G4) {
            g0 += pp[n]; g1 += pp[DD+n]; g2 += pp[2*DD+n]; g3 += pp[3*DD+n];
        }
        float f  = sigm(g0);
        float i  = sigm(g1);
        float o  = sigm(g2);
        float cb = tanhf(g3);
        float ddv = (rg == 0) ? tanhf(u.dd0[((long long)b*TT + t)*DD + n])
                              : u.dd[(long long)(rg-1)*BD + idx];
        float* cp = u.c + (long long)rg*BD;
        float cv = f*cp[idx] + i*cb + ddv;
        cp[idx] = cv;
        float* hp = u.h + (((long long)(t & 3)*LL) + rg)*BD;
        hp[idx] = o * tanhf(cv);
    } else {
        if (!u.pvalid) return;
        float v = u.pb[n] + u.pp[idx] + u.pp[(long long)BB*OO + idx] + u.pp[2ll*BB*OO + idx];
        u.out[((long long)b*TT + u.tp)*OO + n] = v;
    }
}

// ---------------- layer-0 key scan: d0(t) = keys * prod sigm(Grx0) ----------------
__global__ void scan_d0(const float* __restrict__ grx0, const float* __restrict__ keys,
                        float* __restrict__ d0all)
{
    int i = blockIdx.x*256 + threadIdx.x;    // < B*K
    int b = i >> 6, kk = i & 63;
    float d = keys[i];
    for (int t = 0; t < TT; t++) {
        float g = grx0[((long long)b*TT + t)*KK + kk];
        d *= 1.0f/(1.0f + expf(-g));
        d0all[((long long)b*TT + t)*KK + kk] = d;
    }
}

// ---------------- state init (every call; deterministic replays) ----------------
__global__ void init_kernel(float* __restrict__ h, float* __restrict__ c,
                            float* __restrict__ d, const float* __restrict__ keys)
{
    for (long long idx = (long long)blockIdx.x*256 + threadIdx.x;
         idx < 4ll*LL*BD; idx += (long long)gridDim.x*256) {
        h[idx] = 0.0f;
        if (idx < (long long)LL*BD)    c[idx] = 0.0f;
        if (idx < (long long)LL*BB*KK) d[idx] = keys[idx % (BB*KK)];
    }
}

// ---------------- host orchestration ----------------
extern "C" void kernel_launch(void* const* d_in, const int* in_sizes, int n_in,
                              void* d_out, int out_size)
{
    const float* X    = (const float*)d_in[0];
    const float* keys = (const float*)d_in[1];

    const float *wx_w[LL], *wx_b[LL], *wh_w[LL], *wh_b[LL], *wr_w[LL], *wl_w[LL];
    if (in_sizes[4] == 512*2048) {
        for (int l = 0; l < LL; l++) {      // dict order
            int base = 2 + 6*l;
            wx_w[l] = (const float*)d_in[base+0];
            wx_b[l] = (const float*)d_in[base+1];
            wh_w[l] = (const float*)d_in[base+2];
            wh_b[l] = (const float*)d_in[base+3];
            wr_w[l] = (const float*)d_in[base+4];
            wl_w[l] = (const float*)d_in[base+5];
        }
    } else {
        for (int l = 0; l < LL; l++) {      // signature order
            wx_w[l] = (const float*)d_in[2 + 2*l];
            wx_b[l] = (const float*)d_in[3 + 2*l];
            wh_w[l] = (const float*)d_in[8 + 2*l];
            wh_b[l] = (const float*)d_in[9 + 2*l];
            wr_w[l] = (const float*)d_in[14 + l];
            wl_w[l] = (const float*)d_in[17 + l];
        }
    }
    const float* wd     = (const float*)d_in[20];
    const float* proj_w = (const float*)d_in[21];
    const float* proj_b = (const float*)d_in[22];
    float* out = (float*)d_out;

    float *p_gx, *p_Grx, *p_d0all, *p_dd0, *p_h, *p_c, *p_d, *p_dd, *p_part, *p_ppart;
    cudaGetSymbolAddress((void**)&p_gx,    g_gx);
    cudaGetSymbolAddress((void**)&p_Grx,   g_Grx);
    cudaGetSymbolAddress((void**)&p_d0all, g_d0all);
    cudaGetSymbolAddress((void**)&p_dd0,   g_dd0);
    cudaGetSymbolAddress((void**)&p_h,     g_h);
    cudaGetSymbolAddress((void**)&p_c,     g_c);
    cudaGetSymbolAddress((void**)&p_d,     g_d);
    cudaGetSymbolAddress((void**)&p_dd,    g_dd);
    cudaGetSymbolAddress((void**)&p_part,  g_part);
    cudaGetSymbolAddress((void**)&p_ppart, g_ppart);

    auto hptr = [&](int l, int t) {
        return p_h + (((long long)(t & 3)*LL) + l)*BD;
    };

    // reset recurrent state
    init_kernel<<<12288, 256>>>(p_h, p_c, p_d, keys);

    // ---- prologue (x-only, fully parallel) ----
    // Grx_l = X @ wr_w[l][:C]   (N=64, z=3)
    {
        StageArgs SA{};
        for (int i = 0; i < 11; i++) SA.p[i].kind = -1;
        for (int l = 0; l < LL; l++) {
            SA.p[l].A = X;        SA.p[l].lda = CC;
            SA.p[l].Bw = wr_w[l]; SA.p[l].ldb = KK;
            SA.p[l].out = p_Grx + (long long)l*BT*KK; SA.p[l].ldc = KK;
            SA.p[l].K = 512; SA.p[l].xmax = 1; SA.p[l].kind = 0;
        }
        dim3 g(1, BT/64, 3);
        gemm_stage<64,4,8><<<g, 128>>>(SA);
    }
    // layer-0 key path: d0 scan, then dd0 = d0all @ wd (raw)
    scan_d0<<<BB*KK/256, 256>>>(p_Grx, keys, p_d0all);
    {
        StageArgs SA{};
        for (int i = 0; i < 11; i++) SA.p[i].kind = -1;
        SA.p[0].A = p_d0all; SA.p[0].lda = KK;
        SA.p[0].Bw = wd;     SA.p[0].ldb = DD;
        SA.p[0].out = p_dd0; SA.p[0].ldc = DD;
        SA.p[0].K = KK; SA.p[0].xmax = 4; SA.p[0].kind = 0;
        dim3 g(4, BT/64, 1);
        gemm_stage<128,8,8><<<g, 128>>>(SA);
    }
    // Gx_l = X @ wx_w[l][:C]   (big parallel GEMM, z=3)
    {
        StageArgs SA{};
        for (int i = 0; i < 11; i++) SA.p[i].kind = -1;
        for (int l = 0; l < LL; l++) {
            SA.p[l].A = X;        SA.p[l].lda = CC;
            SA.p[l].Bw = wx_w[l]; SA.p[l].ldb = G4;
            SA.p[l].out = p_gx + (long long)l*BT*G4; SA.p[l].ldc = G4;
            SA.p[l].K = 512; SA.p[l].xmax = 16; SA.p[l].kind = 0;
        }
        dim3 g(16, BT/64, 3);
        gemm_stage<128,8,8><<<g, 128>>>(SA);
    }

    // ---- skewed-pipeline serial phase: stage s runs
    //   gate0(t0=s), k1+gate1(t1=s-1), k1+gate2(t2=s-2), proj(tp=s-3)
    // in ONE launch, then one combined update launch.
    for (int s = 0; s <= TT + 2; s++) {
        const int t0 = s, t1 = s - 1, t2 = s - 2, tp = s - 3;
        const bool v0 = (t0 >= 0 && t0 < TT);
        const bool v1 = (t1 >= 0 && t1 < TT);
        const bool v2 = (t2 >= 0 && t2 < TT);
        const bool vp = (tp >= 0 && tp < TT);

        StageArgs SA{};
        for (int i = 0; i < 11; i++) SA.p[i].kind = -1;

        auto setg = [&](int pi, const float* A, const float* Bw, float* o,
                        long long ldb, long long ldc, int xmax) {
            SA.p[pi].A = A;  SA.p[pi].lda = DD;
            SA.p[pi].Bw = Bw; SA.p[pi].ldb = ldb;
            SA.p[pi].out = o; SA.p[pi].ldc = ldc;
            SA.p[pi].K = 512; SA.p[pi].xmax = xmax; SA.p[pi].kind = 0;
        };
        if (v0)
            setg(0, hptr(0, t0-1), wh_w[0], p_part + 0ll*BB*G4, G4, G4, 16);
        if (v1) {
            setg(1, hptr(1, t1-1), wh_w[1],                       p_part + 1ll*BB*G4, G4, G4, 16);
            setg(2, hptr(0, t1),   wx_w[1] + (long long)CC*G4,    p_part + 2ll*BB*G4, G4, G4, 16);
        }
        if (v2) {
            setg(3, hptr(2, t2-1), wh_w[2],                          p_part + 3ll*BB*G4, G4, G4, 16);
            setg(4, hptr(0, t2),   wx_w[2] + (long long)CC*G4,       p_part + 4ll*BB*G4, G4, G4, 16);
            setg(5, hptr(1, t2),   wx_w[2] + (long long)(CC+DD)*G4,  p_part + 5ll*BB*G4, G4, G4, 16);
        }
        if (vp)
            for (int l = 0; l < LL; l++)
                setg(6 + l, hptr(l, tp), proj_w + (long long)l*DD*OO,
                     p_ppart + (long long)l*BB*OO, OO, OO, 4);
        if (v1) {
            SA.p[9].kind = 1;
            K1A& a = SA.k1[0];
            a.hn = p_h + (long long)(t1 & 3)*LL*BD;
            a.hp = p_h + (long long)((t1-1) & 3)*LL*BD;
            a.grx = p_Grx + 1ll*BT*KK;
            a.wr = wr_w[1]; a.wl0 = wl_w[0]; a.wl1 = wl_w[1]; a.wd = wd;
            a.dst = p_d + 1ll*BB*KK; a.dd = p_dd;
            a.l = 1; a.t = t1;
        }
        if (v2) {
            SA.p[10].kind = 2;
            K1A& a = SA.k1[1];
            a.hn = p_h + (long long)(t2 & 3)*LL*BD;
            a.hp = p_h + (long long)((t2-1) & 3)*LL*BD;
            a.grx = p_Grx + 2ll*BT*KK;
            a.wr = wr_w[2]; a.wl0 = wl_w[0]; a.wl1 = wl_w[1]; a.wd = wd;
            a.dst = p_d + 2ll*BB*KK; a.dd = p_dd + BD;
            a.l = 2; a.t = t2;
        }

        dim3 gg(16, BB/64, 11);
        gemm_stage<128,8,8><<<gg, 128>>>(SA);

        UpdA u{};
        u.valid0 = v0; u.valid1 = v1; u.valid2 = v2; u.pvalid = vp;
        u.t0 = t0; u.t1 = t1; u.t2 = t2; u.tp = tp;
        u.gx0 = p_gx + 0ll*BT*G4; u.gx1 = p_gx + 1ll*BT*G4; u.gx2 = p_gx + 2ll*BT*G4;
        u.wxb0 = wx_b[0]; u.wxb1 = wx_b[1]; u.wxb2 = wx_b[2];
        u.whb0 = wh_b[0]; u.whb1 = wh_b[1]; u.whb2 = wh_b[2];
        u.part = p_part; u.dd0 = p_dd0; u.dd = p_dd;
        u.h = p_h; u.c = p_c;
        u.pb = proj_b; u.pp = p_ppart; u.out = out;
        stage_update<<<4096, 256>>>(u);
    }
}

// round 11
// speedup vs baseline: 2.5882x; 1.4177x over previous
#include <cuda_runtime.h>
#include <cuda_bf16.h>
#include <math.h>
#include <stdint.h>

#define BB  512
#define TT  55
#define CC  512
#define DD  512
#define KK  64
#define LL  3
#define OO  512
#define BT  (BB*TT)      // 28160
#define BD  (BB*DD)      // 262144
#define G4  2048

// ---------------- device scratch ----------------
__device__ float g_gx[(size_t)LL*BT*G4];
__device__ float g_Grx[(size_t)LL*BT*KK];
__device__ float g_d0all[(size_t)BT*KK];
__device__ float g_dd0[(size_t)BT*DD];
__device__ float g_h[4*LL*BD];                    // fp32 h ring (k1 reads)
__device__ __nv_bfloat16 g_hbh[4*LL*BD];          // bf16 hi ring
__device__ __nv_bfloat16 g_hbl[4*LL*BD];          // bf16 lo ring
__device__ float g_c[LL*BD];
__device__ float g_d[LL*BB*KK];
__device__ float g_dd[2*BD];
__device__ float g_part[6*(size_t)BB*G4];
__device__ float g_ppart[3*(size_t)BB*OO];
__device__ __nv_bfloat16 g_xbh[(size_t)BT*CC];    // X bf16 hi
__device__ __nv_bfloat16 g_xbl[(size_t)BT*CC];
// pre-transposed bf16 weight images, [n][k=512] row-major (12 images)
#define WIMG_TOT 10223616
__device__ __nv_bfloat16 g_wih[WIMG_TOT];
__device__ __nv_bfloat16 g_wil[WIMG_TOT];

__device__ __forceinline__ float sigm(float x) { return 1.0f/(1.0f+expf(-x)); }

// ---- mma.sync m16n8k16 bf16 (base-target PTX, no 'a' gating) ----
__device__ __forceinline__ void mma16816(float* d, const uint32_t* a, const uint32_t* b) {
    asm volatile("mma.sync.aligned.m16n8k16.row.col.f32.bf16.bf16.f32 "
        "{%0,%1,%2,%3}, {%4,%5,%6,%7}, {%8,%9}, {%0,%1,%2,%3};"
        : "+f"(d[0]), "+f"(d[1]), "+f"(d[2]), "+f"(d[3])
        : "r"(a[0]), "r"(a[1]), "r"(a[2]), "r"(a[3]), "r"(b[0]), "r"(b[1]));
}

// ---------------- key-gate body (256 threads; 8 batches per block) ----------------
struct K1A {
    const float *hp, *hn, *grx, *wr, *wl0, *wl1, *wd;
    float *dst, *dd;
    int l, t;
};
__device__ void k1_body(const K1A& a, int bx)
{
    __shared__ float dn_s[8][KK];
    const int tid = threadIdx.x;        // 256
    const int r   = tid >> 5;           // 0..7
    const int q   = tid & 31;
    const int b   = bx*8 + r;

    const long long gro = ((long long)b*TT + a.t)*KK;
    float acc0 = a.grx[gro + q];
    float acc1 = a.grx[gro + q + 32];
    for (int j = 0; j < a.l; j++) {
        const float* hnj = a.hn + (size_t)j*BD + (size_t)b*DD;
        const float* hpj = a.hp + (size_t)j*BD + (size_t)b*DD;
        const float* wrp = a.wr + (size_t)(CC + j*DD)*KK;
        const float* wlp = (j == 0 ? a.wl0 : a.wl1);
        float u0 = 0.f, u1 = 0.f;
#pragma unroll 4
        for (int m = 0; m < DD; m++) {
            float hv = hnj[m], pv = hpj[m];
            acc0 = fmaf(hv, wrp[(size_t)m*KK + q],      acc0);
            acc1 = fmaf(hv, wrp[(size_t)m*KK + q + 32], acc1);
            u0   = fmaf(pv, wlp[(size_t)m*KK + q],      u0);
            u1   = fmaf(pv, wlp[(size_t)m*KK + q + 32], u1);
        }
        acc0 += u0 * (1.0f/3.0f);
        acc1 += u1 * (1.0f/3.0f);
    }
    float dn0 = sigm(acc0) * a.dst[b*KK + q];
    float dn1 = sigm(acc1) * a.dst[b*KK + q + 32];
    a.dst[b*KK + q]      = dn0;
    a.dst[b*KK + q + 32] = dn1;
    dn_s[r][q]      = dn0;
    dn_s[r][q + 32] = dn1;
    __syncthreads();

    for (int e = tid; e < 8*DD; e += 256) {
        int r2 = e >> 9;
        int n  = e & 511;
        int bb = bx*8 + r2;
        float s = 0.0f;
#pragma unroll
        for (int qq = 0; qq < KK; qq++)
            s = fmaf(dn_s[r2][qq], a.wd[(size_t)qq*DD + n], s);
        a.dd[(size_t)bb*DD + n] = tanhf(s);
    }
}

// ---------------- mma stage kernel: bf16x3 GEMM planes + k1 planes ----------------
// Tile M=128,N=128,K=512 (16 chunks of 32). A row-major bf16 (lda=512); B from
// pre-transposed [n][512] images. 8 warps (2x4), warp tile 64x32 of m16n8k16 atoms.
struct TPlane {
    const __nv_bfloat16 *Ah, *Al;   // [M][512]
    const __nv_bfloat16 *Bh, *Bl;   // image base [Np][512]
    float* out; long long ldc;
    int xmax; int kind;             // 0 gemm, -1 idle, 1 -> k1[0], 2 -> k1[1]
};
struct TStage { TPlane p[11]; K1A k1[2]; };

#define SP 40   // smem row pitch (bf16)

__global__ void __launch_bounds__(256)
mma_stage(TStage SA)
{
    __shared__ __align__(16) __nv_bfloat16 Ah_s[128][SP];
    __shared__ __align__(16) __nv_bfloat16 Al_s[128][SP];
    __shared__ __align__(16) __nv_bfloat16 Bh_s[128][SP];
    __shared__ __align__(16) __nv_bfloat16 Bl_s[128][SP];

    const TPlane pl = SA.p[blockIdx.z];
    if (pl.kind < 0) return;
    if (pl.kind > 0) {
        k1_body(SA.k1[pl.kind - 1], blockIdx.y * gridDim.x + blockIdx.x);
        return;
    }
    if ((int)blockIdx.x >= pl.xmax) return;

    const int tid = threadIdx.x;
    const int wid = tid >> 5, lid = tid & 31;
    const int wm = wid >> 2, wn = wid & 3;         // warp grid 2x4
    const int gid = lid >> 2, tig = lid & 3;
    const int row0 = blockIdx.y * 128;
    const int col0 = blockIdx.x * 128;

    float d[4][4][4];
#pragma unroll
    for (int i = 0; i < 4; i++)
#pragma unroll
        for (int j = 0; j < 4; j++)
#pragma unroll
            for (int e = 0; e < 4; e++) d[i][j][e] = 0.0f;

    for (int kc = 0; kc < 16; kc++) {
        // load 128x32 bf16 tiles (hi+lo for A and B): 512 uint4 per tile pair
#pragma unroll
        for (int it = 0; it < 2; it++) {
            int e   = tid + it*256;       // 0..511
            int r   = e >> 2;             // 0..127
            int sg  = e & 3;              // 16B unit within 32 cols
            size_t ao = (size_t)(row0 + r)*512 + kc*32 + sg*8;
            *(uint4*)&Ah_s[r][sg*8] = *(const uint4*)(pl.Ah + ao);
            *(uint4*)&Al_s[r][sg*8] = *(const uint4*)(pl.Al + ao);
            size_t bo = (size_t)(col0 + r)*512 + kc*32 + sg*8;
            *(uint4*)&Bh_s[r][sg*8] = *(const uint4*)(pl.Bh + bo);
            *(uint4*)&Bl_s[r][sg*8] = *(const uint4*)(pl.Bl + bo);
        }
        __syncthreads();

#pragma unroll
        for (int kk = 0; kk < 32; kk += 16) {
            uint32_t ah[4][4], al[4][4];
#pragma unroll
            for (int i = 0; i < 4; i++) {
                int r = wm*64 + i*16 + gid;
                ah[i][0] = *(const uint32_t*)&Ah_s[r    ][kk + tig*2];
                ah[i][1] = *(const uint32_t*)&Ah_s[r + 8][kk + tig*2];
                ah[i][2] = *(const uint32_t*)&Ah_s[r    ][kk + tig*2 + 8];
                ah[i][3] = *(const uint32_t*)&Ah_s[r + 8][kk + tig*2 + 8];
                al[i][0] = *(const uint32_t*)&Al_s[r    ][kk + tig*2];
                al[i][1] = *(const uint32_t*)&Al_s[r + 8][kk + tig*2];
                al[i][2] = *(const uint32_t*)&Al_s[r    ][kk + tig*2 + 8];
                al[i][3] = *(const uint32_t*)&Al_s[r + 8][kk + tig*2 + 8];
            }
#pragma unroll
            for (int j = 0; j < 4; j++) {
                int nr = wn*32 + j*8 + gid;
                uint32_t bh[2], bl[2];
                bh[0] = *(const uint32_t*)&Bh_s[nr][kk + tig*2];
                bh[1] = *(const uint32_t*)&Bh_s[nr][kk + tig*2 + 8];
                bl[0] = *(const uint32_t*)&Bl_s[nr][kk + tig*2];
                bl[1] = *(const uint32_t*)&Bl_s[nr][kk + tig*2 + 8];
#pragma unroll
                for (int i = 0; i < 4; i++) {
                    mma16816(d[i][j], ah[i], bh);
                    mma16816(d[i][j], al[i], bh);
                    mma16816(d[i][j], ah[i], bl);
                }
            }
        }
        __syncthreads();
    }

    // epilogue: c0,c1 -> row gid; c2,c3 -> row gid+8
#pragma unroll
    for (int i = 0; i < 4; i++) {
        long long r = row0 + wm*64 + i*16 + gid;
#pragma unroll
        for (int j = 0; j < 4; j++) {
            long long cn = col0 + wn*32 + j*8 + tig*2;
            *(float2*)&pl.out[r*pl.ldc + cn]       = make_float2(d[i][j][0], d[i][j][1]);
            *(float2*)&pl.out[(r+8)*pl.ldc + cn]   = make_float2(d[i][j][2], d[i][j][3]);
        }
    }
}

// ---------------- scalar segmented SGEMM (prologue Grx / dd0 only) ----------------
__device__ __forceinline__ void fma2(unsigned long long &d, unsigned long long a, unsigned long long b){
    asm("fma.rn.f32x2 %0, %1, %2, %0;" : "+l"(d) : "l"(a), "l"(b));
}
struct SPlane { const float* A; long long lda; const float* Bw; long long ldb;
                float* out; long long ldc; int K; int xmax; int kind; };
struct SStage { SPlane p[3]; };

template<int BN, int TM, int TN>
__global__ void __launch_bounds__((BN/TN)*(64/TM))
gemm_s(SStage SA)
{
    constexpr int BM = 64, BK = 16;
    constexpr int TX = BN/TN, TY = BM/TM, NT = TX*TY;
    constexpr int AW = 2*BM + 8;
    __shared__ __align__(16) float a_s[BK][AW];
    __shared__ __align__(16) float b_s[BK][BN];

    const SPlane pl = SA.p[blockIdx.z];
    if (pl.kind < 0) return;
    if ((int)blockIdx.x >= pl.xmax) return;

    const int tid  = threadIdx.x;
    const int tx   = tid % TX;
    const int ty   = tid / TX;
    const int row0 = blockIdx.y * BM;
    const int col0 = blockIdx.x * BN;

    unsigned long long acc[TM][TN/2];
#pragma unroll
    for (int i = 0; i < TM; i++)
#pragma unroll
        for (int j = 0; j < TN/2; j++) acc[i][j] = 0ull;

    for (int k0 = 0; k0 < pl.K; k0 += BK) {
#pragma unroll
        for (int e = tid; e < BM*BK/4; e += NT) {
            int r  = e >> 2;
            int kq = (e & 3) << 2;
            float4 v = *(const float4*)(pl.A + (long long)(row0 + r)*pl.lda + k0 + kq);
            *(float2*)&a_s[kq+0][2*r] = make_float2(v.x, v.x);
            *(float2*)&a_s[kq+1][2*r] = make_float2(v.y, v.y);
            *(float2*)&a_s[kq+2][2*r] = make_float2(v.z, v.z);
            *(float2*)&a_s[kq+3][2*r] = make_float2(v.w, v.w);
        }
#pragma unroll
        for (int e = tid; e < BK*BN/4; e += NT) {
            int kk = e / (BN/4);
            int n4 = (e % (BN/4)) * 4;
            *(float4*)&b_s[kk][n4] =
                *(const float4*)(pl.Bw + (long long)(k0+kk)*pl.ldb + col0 + n4);
        }
        __syncthreads();
#pragma unroll
        for (int kk = 0; kk < BK; kk++) {
            unsigned long long aa[TM], bq[TN/2];
            const ulonglong2* ap = (const ulonglong2*)&a_s[kk][2*(ty*TM)];
            const ulonglong2* bp = (const ulonglong2*)&b_s[kk][tx*TN];
#pragma unroll
            for (int i = 0; i < TM/2; i++) { ulonglong2 u = ap[i]; aa[2*i] = u.x; aa[2*i+1] = u.y; }
#pragma unroll
            for (int j = 0; j < TN/4; j++) { ulonglong2 v = bp[j]; bq[2*j] = v.x; bq[2*j+1] = v.y; }
#pragma unroll
            for (int i = 0; i < TM; i++)
#pragma unroll
                for (int j = 0; j < TN/2; j++)
                    fma2(acc[i][j], aa[i], bq[j]);
        }
        __syncthreads();
    }
#pragma unroll
    for (int i = 0; i < TM; i++) {
        long long r = row0 + ty*TM + i;
        float* orow = pl.out + r*pl.ldc + col0 + tx*TN;
#pragma unroll
        for (int j = 0; j < TN/2; j++)
            *(unsigned long long*)&orow[2*j] = acc[i][j];
    }
}

// ---------------- combined stage update (+ bf16 hi/lo h write) ----------------
struct UpdA {
    int valid0, valid1, valid2, pvalid;
    int t0, t1, t2, tp;
    const float *gx0, *gx1, *gx2;
    const float *wxb0, *wxb1, *wxb2, *whb0, *whb1, *whb2;
    const float *part, *dd0, *dd;
    float *h, *c;
    const float *pb; const float *pp; float *out;
};

__global__ void stage_update(UpdA u)
{
    const int rg = blockIdx.x >> 10;
    const long long idx = ((long long)(blockIdx.x & 1023))*256 + threadIdx.x;
    const int b = (int)(idx >> 9);
    const int n = (int)(idx & 511);

    if (rg < 3) {
        int valid = rg==0 ? u.valid0 : (rg==1 ? u.valid1 : u.valid2);
        if (!valid) return;
        int t = rg==0 ? u.t0 : (rg==1 ? u.t1 : u.t2);
        const float* gx  = rg==0 ? u.gx0  : (rg==1 ? u.gx1  : u.gx2);
        const float* wxb = rg==0 ? u.wxb0 : (rg==1 ? u.wxb1 : u.wxb2);
        const float* whb = rg==0 ? u.whb0 : (rg==1 ? u.whb1 : u.whb2);
        int pbase = rg==0 ? 0 : (rg==1 ? 1 : 3);
        int np    = rg + 1;

        const float* gxr = gx + ((long long)b*TT + t)*G4;
        float g0 = gxr[n]        + wxb[n]        + whb[n];
        float g1 = gxr[DD+n]     + wxb[DD+n]     + whb[DD+n];
        float g2 = gxr[2*DD+n]   + wxb[2*DD+n]   + whb[2*DD+n];
        float g3 = gxr[3*DD+n]   + wxb[3*DD+n]   + whb[3*DD+n];
        const float* pp = u.part + (long long)pbase*BB*G4 + (long long)b*G4;
        for (int z = 0; z < np; z++, pp += (long long)BB*G4) {
            g0 += pp[n]; g1 += pp[DD+n]; g2 += pp[2*DD+n]; g3 += pp[3*DD+n];
        }
        float f  = sigm(g0);
        float i  = sigm(g1);
        float o  = sigm(g2);
        float cb = tanhf(g3);
        float ddv = (rg == 0) ? tanhf(u.dd0[((long long)b*TT + t)*DD + n])
                              : u.dd[(long long)(rg-1)*BD + idx];
        float* cp = u.c + (long long)rg*BD;
        float cv = f*cp[idx] + i*cb + ddv;
        cp[idx] = cv;
        float hv = o * tanhf(cv);
        long long hoff = (((long long)(t & 3)*LL) + rg)*BD + idx;
        u.h[hoff] = hv;
        __nv_bfloat16 bh = __float2bfloat16(hv);
        g_hbh[hoff] = bh;
        g_hbl[hoff] = __float2bfloat16(hv - __bfloat162float(bh));
    } else {
        if (!u.pvalid) return;
        float v = u.pb[n] + u.pp[idx] + u.pp[(long long)BB*OO + idx] + u.pp[2ll*BB*OO + idx];
        u.out[((long long)b*TT + u.tp)*OO + n] = v;
    }
}

// ---------------- weight image prep: transpose + bf16 hi/lo split ----------------
// image[n][k] = W[k][n], k = 0..511 contiguous
struct WImg { const float* src; int N; long long off; };
struct WTab { WImg im[12]; };

__global__ void wprep(WTab T)
{
    WImg im = T.im[blockIdx.z];
    int idx = blockIdx.x*256 + threadIdx.x;       // over N*64 8-elem units
    if (idx >= im.N*64) return;
    int n  = idx >> 6;
    int ku = idx & 63;
    __nv_bfloat16 hi[8], lo[8];
#pragma unroll
    for (int j = 0; j < 8; j++) {
        float w = im.src[(size_t)(ku*8 + j)*im.N + n];
        __nv_bfloat16 h = __float2bfloat16(w);
        hi[j] = h;
        lo[j] = __float2bfloat16(w - __bfloat162float(h));
    }
    size_t d = (size_t)im.off + (size_t)n*512 + (size_t)ku*8;
    *(uint4*)&g_wih[d] = *(uint4*)hi;
    *(uint4*)&g_wil[d] = *(uint4*)lo;
}

// ---------------- X -> bf16 hi/lo ----------------
__global__ void xconv(const float* __restrict__ X)
{
    long long i4 = ((long long)blockIdx.x*256 + threadIdx.x);
    const float4 v = *(const float4*)(X + i4*4);
    __nv_bfloat16 hi[4], lo[4];
    float xs[4] = {v.x, v.y, v.z, v.w};
#pragma unroll
    for (int j = 0; j < 4; j++) {
        hi[j] = __float2bfloat16(xs[j]);
        lo[j] = __float2bfloat16(xs[j] - __bfloat162float(hi[j]));
    }
    *(uint2*)&g_xbh[i4*4] = *(uint2*)hi;
    *(uint2*)&g_xbl[i4*4] = *(uint2*)lo;
}

// ---------------- layer-0 key scan ----------------
__global__ void scan_d0(const float* __restrict__ grx0, const float* __restrict__ keys,
                        float* __restrict__ d0all)
{
    int i = blockIdx.x*256 + threadIdx.x;
    int b = i >> 6, kk = i & 63;
    float d = keys[i];
    for (int t = 0; t < TT; t++) {
        float g = grx0[((long long)b*TT + t)*KK + kk];
        d *= 1.0f/(1.0f + expf(-g));
        d0all[((long long)b*TT + t)*KK + kk] = d;
    }
}

// ---------------- state init ----------------
__global__ void init_kernel(float* __restrict__ h, float* __restrict__ c,
                            float* __restrict__ d, const float* __restrict__ keys)
{
    const __nv_bfloat16 z16 = __float2bfloat16(0.0f);
    for (long long idx = (long long)blockIdx.x*256 + threadIdx.x;
         idx < 4ll*LL*BD; idx += (long long)gridDim.x*256) {
        h[idx] = 0.0f;
        g_hbh[idx] = z16;
        g_hbl[idx] = z16;
        if (idx < (long long)LL*BD)    c[idx] = 0.0f;
        if (idx < (long long)LL*BB*KK) d[idx] = keys[idx % (BB*KK)];
    }
}

// ---------------- host orchestration ----------------
static const long long IMG_OFF[12] = {
    0, 1048576, 2097152, 3145728, 4194304, 5242880,            // gate planes 0..5
    6291456, 6553600, 6815744,                                 // proj 0..2
    7077888, 8126464, 9175040                                  // gx 0..2
};

extern "C" void kernel_launch(void* const* d_in, const int* in_sizes, int n_in,
                              void* d_out, int out_size)
{
    const float* X    = (const float*)d_in[0];
    const float* keys = (const float*)d_in[1];

    const float *wx_w[LL], *wx_b[LL], *wh_w[LL], *wh_b[LL], *wr_w[LL], *wl_w[LL];
    if (in_sizes[4] == 512*2048) {
        for (int l = 0; l < LL; l++) {      // dict order
            int base = 2 + 6*l;
            wx_w[l] = (const float*)d_in[base+0];
            wx_b[l] = (const float*)d_in[base+1];
            wh_w[l] = (const float*)d_in[base+2];
            wh_b[l] = (const float*)d_in[base+3];
            wr_w[l] = (const float*)d_in[base+4];
            wl_w[l] = (const float*)d_in[base+5];
        }
    } else {
        for (int l = 0; l < LL; l++) {      // signature order
            wx_w[l] = (const float*)d_in[2 + 2*l];
            wx_b[l] = (const float*)d_in[3 + 2*l];
            wh_w[l] = (const float*)d_in[8 + 2*l];
            wh_b[l] = (const float*)d_in[9 + 2*l];
            wr_w[l] = (const float*)d_in[14 + l];
            wl_w[l] = (const float*)d_in[17 + l];
        }
    }
    const float* wd     = (const float*)d_in[20];
    const float* proj_w = (const float*)d_in[21];
    const float* proj_b = (const float*)d_in[22];
    float* out = (float*)d_out;

    float *p_gx, *p_Grx, *p_d0all, *p_dd0, *p_h, *p_c, *p_d, *p_dd, *p_part, *p_ppart;
    __nv_bfloat16 *p_wih, *p_wil, *p_xbh, *p_xbl, *p_hbh, *p_hbl;
    cudaGetSymbolAddress((void**)&p_gx,    g_gx);
    cudaGetSymbolAddress((void**)&p_Grx,   g_Grx);
    cudaGetSymbolAddress((void**)&p_d0all, g_d0all);
    cudaGetSymbolAddress((void**)&p_dd0,   g_dd0);
    cudaGetSymbolAddress((void**)&p_h,     g_h);
    cudaGetSymbolAddress((void**)&p_c,     g_c);
    cudaGetSymbolAddress((void**)&p_d,     g_d);
    cudaGetSymbolAddress((void**)&p_dd,    g_dd);
    cudaGetSymbolAddress((void**)&p_part,  g_part);
    cudaGetSymbolAddress((void**)&p_ppart, g_ppart);
    cudaGetSymbolAddress((void**)&p_wih,   g_wih);
    cudaGetSymbolAddress((void**)&p_wil,   g_wil);
    cudaGetSymbolAddress((void**)&p_xbh,   g_xbh);
    cudaGetSymbolAddress((void**)&p_xbl,   g_xbl);
    cudaGetSymbolAddress((void**)&p_hbh,   g_hbh);
    cudaGetSymbolAddress((void**)&p_hbl,   g_hbl);

    auto hbh = [&](int l, int t) {
        int slot = (t < 0) ? 3 : (t & 3);
        return p_hbh + (((long long)slot*LL) + l)*BD;
    };
    auto hbl = [&](int l, int t) {
        int slot = (t < 0) ? 3 : (t & 3);
        return p_hbl + (((long long)slot*LL) + l)*BD;
    };

    // ---- prologue ----
    init_kernel<<<12288, 256>>>(p_h, p_c, p_d, keys);

    {
        WTab T{};
        T.im[0] = { wh_w[0], G4, IMG_OFF[0] };
        T.im[1] = { wh_w[1], G4, IMG_OFF[1] };
        T.im[2] = { wx_w[1] + (long long)CC*G4, G4, IMG_OFF[2] };
        T.im[3] = { wh_w[2], G4, IMG_OFF[3] };
        T.im[4] = { wx_w[2] + (long long)CC*G4, G4, IMG_OFF[4] };
        T.im[5] = { wx_w[2] + (long long)(CC+DD)*G4, G4, IMG_OFF[5] };
        for (int l = 0; l < LL; l++)
            T.im[6+l] = { proj_w + (long long)l*DD*OO, OO, IMG_OFF[6+l] };
        for (int l = 0; l < LL; l++)
            T.im[9+l] = { wx_w[l], G4, IMG_OFF[9+l] };
        dim3 g(512, 1, 12);
        wprep<<<g, 256>>>(T);
    }
    xconv<<<(BT*CC/4)/256, 256>>>(X);

    // Grx (scalar, N=64, z=3)
    {
        SStage SA{};
        for (int l = 0; l < LL; l++)
            SA.p[l] = { X, CC, wr_w[l], KK, p_Grx + (long long)l*BT*KK, KK, 512, 1, 0 };
        dim3 g(1, BT/64, 3);
        gemm_s<64,4,8><<<g, 128>>>(SA);
    }
    scan_d0<<<BB*KK/256, 256>>>(p_Grx, keys, p_d0all);
    {
        SStage SA{};
        SA.p[0] = { p_d0all, KK, wd, DD, p_dd0, DD, KK, 4, 0 };
        SA.p[1].kind = -1; SA.p[2].kind = -1;
        dim3 g(4, BT/64, 1);
        gemm_s<128,8,8><<<g, 128>>>(SA);
    }
    // Gx (tensor mma, z=3)
    {
        TStage SA{};
        for (int i = 0; i < 11; i++) SA.p[i].kind = -1;
        for (int l = 0; l < LL; l++)
            SA.p[l] = { p_xbh, p_xbl, p_wih + IMG_OFF[9+l], p_wil + IMG_OFF[9+l],
                        p_gx + (long long)l*BT*G4, G4, 16, 0 };
        dim3 g(16, BT/128, 3);
        mma_stage<<<g, 256>>>(SA);
    }

    // ---- skewed-pipeline serial phase ----
    for (int s = 0; s <= TT + 2; s++) {
        const int t0 = s, t1 = s - 1, t2 = s - 2, tp = s - 3;
        const bool v0 = (t0 >= 0 && t0 < TT);
        const bool v1 = (t1 >= 0 && t1 < TT);
        const bool v2 = (t2 >= 0 && t2 < TT);
        const bool vp = (tp >= 0 && tp < TT);

        TStage SA{};
        for (int i = 0; i < 11; i++) SA.p[i].kind = -1;

        auto setg = [&](int pi, int al, int at, int img, float* o, long long ldc, int xmax) {
            SA.p[pi] = { hbh(al, at), hbl(al, at),
                         p_wih + IMG_OFF[img], p_wil + IMG_OFF[img],
                         o, ldc, xmax, 0 };
        };
        if (v0)
            setg(0, 0, t0-1, 0, p_part + 0ll*BB*G4, G4, 16);
        if (v1) {
            setg(1, 1, t1-1, 1, p_part + 1ll*BB*G4, G4, 16);
            setg(2, 0, t1,   2, p_part + 2ll*BB*G4, G4, 16);
        }
        if (v2) {
            setg(3, 2, t2-1, 3, p_part + 3ll*BB*G4, G4, 16);
            setg(4, 0, t2,   4, p_part + 4ll*BB*G4, G4, 16);
            setg(5, 1, t2,   5, p_part + 5ll*BB*G4, G4, 16);
        }
        if (vp)
            for (int l = 0; l < LL; l++)
                setg(6+l, l, tp, 6+l, p_ppart + (long long)l*BB*OO, OO, 4);

        if (v1) {
            SA.p[9].kind = 1;
            K1A& a = SA.k1[0];
            a.hn = p_h + (long long)(t1 & 3)*LL*BD;
            a.hp = p_h + (long long)((t1-1) & 3)*LL*BD;
            a.grx = p_Grx + 1ll*BT*KK;
            a.wr = wr_w[1]; a.wl0 = wl_w[0]; a.wl1 = wl_w[1]; a.wd = wd;
            a.dst = p_d + 1ll*BB*KK; a.dd = p_dd;
            a.l = 1; a.t = t1;
        }
        if (v2) {
            SA.p[10].kind = 2;
            K1A& a = SA.k1[1];
            a.hn = p_h + (long long)(t2 & 3)*LL*BD;
            a.hp = p_h + (long long)((t2-1) & 3)*LL*BD;
            a.grx = p_Grx + 2ll*BT*KK;
            a.wr = wr_w[2]; a.wl0 = wl_w[0]; a.wl1 = wl_w[1]; a.wd = wd;
            a.dst = p_d + 2ll*BB*KK; a.dd = p_dd + BD;
            a.l = 2; a.t = t2;
        }

        dim3 gg(16, 4, 11);
        mma_stage<<<gg, 256>>>(SA);

        UpdA u{};
        u.valid0 = v0; u.valid1 = v1; u.valid2 = v2; u.pvalid = vp;
        u.t0 = t0; u.t1 = t1; u.t2 = t2; u.tp = tp;
        u.gx0 = p_gx + 0ll*BT*G4; u.gx1 = p_gx + 1ll*BT*G4; u.gx2 = p_gx + 2ll*BT*G4;
        u.wxb0 = wx_b[0]; u.wxb1 = wx_b[1]; u.wxb2 = wx_b[2];
        u.whb0 = wh_b[0]; u.whb1 = wh_b[1]; u.whb2 = wh_b[2];
        u.part = p_part; u.dd0 = p_dd0; u.dd = p_dd;
        u.h = p_h; u.c = p_c;
        u.pb = proj_b; u.pp = p_ppart; u.out = out;
        stage_update<<<4096, 256>>>(u);
    }
}

// round 12
// speedup vs baseline: 2.8104x; 1.0859x over previous
#include <cuda_runtime.h>
#include <cuda_bf16.h>
#include <math.h>
#include <stdint.h>

#define BB  512
#define TT  55
#define CC  512
#define DD  512
#define KK  64
#define LL  3
#define OO  512
#define BT  (BB*TT)      // 28160
#define BD  (BB*DD)      // 262144
#define G4  2048

// ---------------- device scratch ----------------
__device__ float g_gx[(size_t)LL*BT*G4];
__device__ float g_Grx[(size_t)LL*BT*KK];
__device__ float g_d0all[(size_t)BT*KK];
__device__ float g_dd0[(size_t)BT*DD];
__device__ float g_h[4*LL*BD];                    // fp32 h ring (k1 reads)
__device__ __nv_bfloat16 g_hbh[4*LL*BD];          // bf16 hi ring
__device__ __nv_bfloat16 g_hbl[4*LL*BD];          // bf16 lo ring
__device__ float g_c[LL*BD];
__device__ float g_d[LL*BB*KK];
__device__ float g_dd[2*BD];
__device__ float g_part[6*(size_t)BB*G4];
__device__ float g_ppart[3*(size_t)BB*OO];
__device__ __nv_bfloat16 g_xbh[(size_t)BT*CC];    // X bf16 hi
__device__ __nv_bfloat16 g_xbl[(size_t)BT*CC];
// pre-transposed bf16 weight images, [n][k=512] row-major (12 images)
#define WIMG_TOT 10223616
__device__ __nv_bfloat16 g_wih[WIMG_TOT];
__device__ __nv_bfloat16 g_wil[WIMG_TOT];

__device__ __forceinline__ float sigm(float x) { return 1.0f/(1.0f+expf(-x)); }

// ---- mma.sync m16n8k16 bf16 (base-target PTX) ----
__device__ __forceinline__ void mma16816(float* d, const uint32_t* a, const uint32_t* b) {
    asm volatile("mma.sync.aligned.m16n8k16.row.col.f32.bf16.bf16.f32 "
        "{%0,%1,%2,%3}, {%4,%5,%6,%7}, {%8,%9}, {%0,%1,%2,%3};"
        : "+f"(d[0]), "+f"(d[1]), "+f"(d[2]), "+f"(d[3])
        : "r"(a[0]), "r"(a[1]), "r"(a[2]), "r"(a[3]), "r"(b[0]), "r"(b[1]));
}
__device__ __forceinline__ void ldsm_x4(uint32_t* r, uint32_t addr) {
    asm volatile("ldmatrix.sync.aligned.m8n8.x4.shared.b16 {%0,%1,%2,%3}, [%4];"
        : "=r"(r[0]), "=r"(r[1]), "=r"(r[2]), "=r"(r[3]) : "r"(addr));
}
__device__ __forceinline__ uint32_t smem_u32(const void* p) {
    uint32_t a;
    asm("{ .reg .u64 t; cvta.to.shared.u64 t, %1; cvt.u32.u64 %0, t; }" : "=r"(a) : "l"(p));
    return a;
}
__device__ __forceinline__ void cp16(uint32_t dst, const void* src) {
    asm volatile("cp.async.cg.shared.global [%0], [%1], 16;" :: "r"(dst), "l"(src));
}
__device__ __forceinline__ void cp_commit() {
    asm volatile("cp.async.commit_group;" ::: "memory");
}
template<int N> __device__ __forceinline__ void cp_wait() {
    asm volatile("cp.async.wait_group %0;" :: "n"(N) : "memory");
}

// ---------------- key-gate body (256 threads; 8 batches per block) ----------------
struct K1A {
    const float *hp, *hn, *grx, *wr, *wl0, *wl1, *wd;
    float *dst, *dd;
    int l, t;
};
__device__ void k1_body(const K1A& a, int bx)
{
    __shared__ float dn_s[8][KK];
    const int tid = threadIdx.x;        // 256
    const int r   = tid >> 5;           // 0..7
    const int q   = tid & 31;
    const int b   = bx*8 + r;

    const long long gro = ((long long)b*TT + a.t)*KK;
    float acc0 = a.grx[gro + q];
    float acc1 = a.grx[gro + q + 32];
    for (int j = 0; j < a.l; j++) {
        const float* hnj = a.hn + (size_t)j*BD + (size_t)b*DD;
        const float* hpj = a.hp + (size_t)j*BD + (size_t)b*DD;
        const float* wrp = a.wr + (size_t)(CC + j*DD)*KK;
        const float* wlp = (j == 0 ? a.wl0 : a.wl1);
        float u0 = 0.f, u1 = 0.f;
#pragma unroll 4
        for (int m = 0; m < DD; m++) {
            float hv = hnj[m], pv = hpj[m];
            acc0 = fmaf(hv, wrp[(size_t)m*KK + q],      acc0);
            acc1 = fmaf(hv, wrp[(size_t)m*KK + q + 32], acc1);
            u0   = fmaf(pv, wlp[(size_t)m*KK + q],      u0);
            u1   = fmaf(pv, wlp[(size_t)m*KK + q + 32], u1);
        }
        acc0 += u0 * (1.0f/3.0f);
        acc1 += u1 * (1.0f/3.0f);
    }
    float dn0 = sigm(acc0) * a.dst[b*KK + q];
    float dn1 = sigm(acc1) * a.dst[b*KK + q + 32];
    a.dst[b*KK + q]      = dn0;
    a.dst[b*KK + q + 32] = dn1;
    dn_s[r][q]      = dn0;
    dn_s[r][q + 32] = dn1;
    __syncthreads();

    for (int e = tid; e < 8*DD; e += 256) {
        int r2 = e >> 9;
        int n  = e & 511;
        int bb = bx*8 + r2;
        float s = 0.0f;
#pragma unroll
        for (int qq = 0; qq < KK; qq++)
            s = fmaf(dn_s[r2][qq], a.wd[(size_t)qq*DD + n], s);
        a.dd[(size_t)bb*DD + n] = tanhf(s);
    }
}

// ---------------- mma stage kernel: cp.async + ldmatrix + bf16x3 HMMA ----------------
// Tile M=128,N=128,K=512 (16 chunks of 32, double-buffered). A row-major bf16 (lda=512);
// B from pre-transposed [n][512] images. 8 warps (2x4), warp tile 64x32.
struct TPlane {
    const __nv_bfloat16 *Ah, *Al;   // [M][512]
    const __nv_bfloat16 *Bh, *Bl;   // image base [Np][512]
    float* out; long long ldc;
    int xmax; int kind;             // 0 gemm, -1 idle, 1 -> k1[0], 2 -> k1[1]
};
struct TStage { TPlane p[11]; K1A k1[2]; };

#define SPB   80        // smem row pitch in BYTES (40 bf16)
#define TILEB 10240     // one 128x32 tile (bytes) with pitch
#define STGB  40960     // 4 tiles per stage
#define NKC   16

__global__ void __launch_bounds__(256)
mma_stage(TStage SA)
{
    extern __shared__ __align__(16) char sm[];

    const TPlane pl = SA.p[blockIdx.z];
    if (pl.kind < 0) return;
    if (pl.kind > 0) {
        k1_body(SA.k1[pl.kind - 1], blockIdx.y * gridDim.x + blockIdx.x);
        return;
    }
    if ((int)blockIdx.x >= pl.xmax) return;

    const int tid = threadIdx.x;
    const int wid = tid >> 5, lid = tid & 31;
    const int wm = wid >> 2, wn = wid & 3;         // warp grid 2x4
    const int gid = lid >> 2, tig = lid & 3;
    const int row0 = blockIdx.y * 128;
    const int col0 = blockIdx.x * 128;
    const uint32_t smb = smem_u32(sm);

    // cp.async mapping: thread handles tile rows r=(tid+it*256)>>2, 16B unit sg
    const int cr0 = tid >> 2, csg = tid & 3;       // it=0
    const int cr1 = (tid + 256) >> 2;              // it=1 (same sg)

    float d[4][4][4];
#pragma unroll
    for (int i = 0; i < 4; i++)
#pragma unroll
        for (int j = 0; j < 4; j++)
#pragma unroll
            for (int e = 0; e < 4; e++) d[i][j][e] = 0.0f;

    auto copy_tiles = [&](int kc, int s) {
        uint32_t sb = smb + s*STGB;
        const size_t ka = (size_t)kc*32 + csg*8;
#pragma unroll
        for (int it = 0; it < 2; it++) {
            int r = it ? cr1 : cr0;
            uint32_t doff = (uint32_t)r*SPB + csg*16;
            cp16(sb + doff,           pl.Ah + (size_t)(row0 + r)*512 + ka);
            cp16(sb + TILEB + doff,   pl.Al + (size_t)(row0 + r)*512 + ka);
            cp16(sb + 2*TILEB + doff, pl.Bh + (size_t)(col0 + r)*512 + ka);
            cp16(sb + 3*TILEB + doff, pl.Bl + (size_t)(col0 + r)*512 + ka);
        }
    };

    // ldmatrix lane-address components (bytes)
    const uint32_t aRow = (uint32_t)(wm*64 + (lid & 15));      // + i*16
    const uint32_t aK   = (uint32_t)((lid >> 4) * 8);          // + kkh
    const uint32_t bN   = (uint32_t)(wn*32 + ((lid >> 4) & 1)*8 + (lid & 7));  // + blk*16
    const uint32_t bK   = (uint32_t)(((lid >> 3) & 1) * 8);    // + kkh

    copy_tiles(0, 0); cp_commit();
    int buf = 0;
    for (int kc = 0; kc < NKC; kc++) {
        if (kc + 1 < NKC) { copy_tiles(kc + 1, buf ^ 1); cp_commit(); cp_wait<1>(); }
        else              { cp_wait<0>(); }
        __syncthreads();

        const uint32_t ah_b = smb + buf*STGB;
        const uint32_t al_b = ah_b + TILEB;
        const uint32_t bh_b = ah_b + 2*TILEB;
        const uint32_t bl_b = ah_b + 3*TILEB;

#pragma unroll
        for (int kkh = 0; kkh < 32; kkh += 16) {
            // B fragments: 2 x4 per hi/lo covering all 4 j-blocks
            uint32_t bh[4][2], bl[4][2];
#pragma unroll
            for (int blk = 0; blk < 2; blk++) {
                uint32_t off = (bN + blk*16)*SPB + (bK + kkh)*2;
                uint32_t t[4];
                ldsm_x4(t, bh_b + off);
                bh[2*blk][0] = t[0]; bh[2*blk][1] = t[1];
                bh[2*blk+1][0] = t[2]; bh[2*blk+1][1] = t[3];
                ldsm_x4(t, bl_b + off);
                bl[2*blk][0] = t[0]; bl[2*blk][1] = t[1];
                bl[2*blk+1][0] = t[2]; bl[2*blk+1][1] = t[3];
            }
#pragma unroll
            for (int i = 0; i < 4; i++) {
                uint32_t off = (aRow + i*16)*SPB + (aK + kkh)*2;
                uint32_t ah[4], al[4];
                ldsm_x4(ah, ah_b + off);
                ldsm_x4(al, al_b + off);
#pragma unroll
                for (int j = 0; j < 4; j++) {
                    mma16816(d[i][j], ah, bh[j]);
                    mma16816(d[i][j], al, bh[j]);
                    mma16816(d[i][j], ah, bl[j]);
                }
            }
        }
        __syncthreads();
        buf ^= 1;
    }

    // epilogue: c0,c1 -> row gid; c2,c3 -> row gid+8
#pragma unroll
    for (int i = 0; i < 4; i++) {
        long long r = row0 + wm*64 + i*16 + gid;
#pragma unroll
        for (int j = 0; j < 4; j++) {
            long long cn = col0 + wn*32 + j*8 + tig*2;
            *(float2*)&pl.out[r*pl.ldc + cn]       = make_float2(d[i][j][0], d[i][j][1]);
            *(float2*)&pl.out[(r+8)*pl.ldc + cn]   = make_float2(d[i][j][2], d[i][j][3]);
        }
    }
}

// ---------------- scalar segmented SGEMM (prologue Grx / dd0 only) ----------------
__device__ __forceinline__ void fma2(unsigned long long &d, unsigned long long a, unsigned long long b){
    asm("fma.rn.f32x2 %0, %1, %2, %0;" : "+l"(d) : "l"(a), "l"(b));
}
struct SPlane { const float* A; long long lda; const float* Bw; long long ldb;
                float* out; long long ldc; int K; int xmax; int kind; };
struct SStage { SPlane p[3]; };

template<int BN, int TM, int TN>
__global__ void __launch_bounds__((BN/TN)*(64/TM))
gemm_s(SStage SA)
{
    constexpr int BM = 64, BK = 16;
    constexpr int TX = BN/TN, TY = BM/TM, NT = TX*TY;
    constexpr int AW = 2*BM + 8;
    __shared__ __align__(16) float a_s[BK][AW];
    __shared__ __align__(16) float b_s[BK][BN];

    const SPlane pl = SA.p[blockIdx.z];
    if (pl.kind < 0) return;
    if ((int)blockIdx.x >= pl.xmax) return;

    const int tid  = threadIdx.x;
    const int tx   = tid % TX;
    const int ty   = tid / TX;
    const int row0 = blockIdx.y * BM;
    const int col0 = blockIdx.x * BN;

    unsigned long long acc[TM][TN/2];
#pragma unroll
    for (int i = 0; i < TM; i++)
#pragma unroll
        for (int j = 0; j < TN/2; j++) acc[i][j] = 0ull;

    for (int k0 = 0; k0 < pl.K; k0 += BK) {
#pragma unroll
        for (int e = tid; e < BM*BK/4; e += NT) {
            int r  = e >> 2;
            int kq = (e & 3) << 2;
            float4 v = *(const float4*)(pl.A + (long long)(row0 + r)*pl.lda + k0 + kq);
            *(float2*)&a_s[kq+0][2*r] = make_float2(v.x, v.x);
            *(float2*)&a_s[kq+1][2*r] = make_float2(v.y, v.y);
            *(float2*)&a_s[kq+2][2*r] = make_float2(v.z, v.z);
            *(float2*)&a_s[kq+3][2*r] = make_float2(v.w, v.w);
        }
#pragma unroll
        for (int e = tid; e < BK*BN/4; e += NT) {
            int kk = e / (BN/4);
            int n4 = (e % (BN/4)) * 4;
            *(float4*)&b_s[kk][n4] =
                *(const float4*)(pl.Bw + (long long)(k0+kk)*pl.ldb + col0 + n4);
        }
        __syncthreads();
#pragma unroll
        for (int kk = 0; kk < BK; kk++) {
            unsigned long long aa[TM], bq[TN/2];
            const ulonglong2* ap = (const ulonglong2*)&a_s[kk][2*(ty*TM)];
            const ulonglong2* bp = (const ulonglong2*)&b_s[kk][tx*TN];
#pragma unroll
            for (int i = 0; i < TM/2; i++) { ulonglong2 u = ap[i]; aa[2*i] = u.x; aa[2*i+1] = u.y; }
#pragma unroll
            for (int j = 0; j < TN/4; j++) { ulonglong2 v = bp[j]; bq[2*j] = v.x; bq[2*j+1] = v.y; }
#pragma unroll
            for (int i = 0; i < TM; i++)
#pragma unroll
                for (int j = 0; j < TN/2; j++)
                    fma2(acc[i][j], aa[i], bq[j]);
        }
        __syncthreads();
    }
#pragma unroll
    for (int i = 0; i < TM; i++) {
        long long r = row0 + ty*TM + i;
        float* orow = pl.out + r*pl.ldc + col0 + tx*TN;
#pragma unroll
        for (int j = 0; j < TN/2; j++)
            *(unsigned long long*)&orow[2*j] = acc[i][j];
    }
}

// ---------------- combined stage update (+ bf16 hi/lo h write) ----------------
struct UpdA {
    int valid0, valid1, valid2, pvalid;
    int t0, t1, t2, tp;
    const float *gx0, *gx1, *gx2;
    const float *wxb0, *wxb1, *wxb2, *whb0, *whb1, *whb2;
    const float *part, *dd0, *dd;
    float *h, *c;
    const float *pb; const float *pp; float *out;
};

__global__ void stage_update(UpdA u)
{
    const int rg = blockIdx.x >> 10;
    const long long idx = ((long long)(blockIdx.x & 1023))*256 + threadIdx.x;
    const int b = (int)(idx >> 9);
    const int n = (int)(idx & 511);

    if (rg < 3) {
        int valid = rg==0 ? u.valid0 : (rg==1 ? u.valid1 : u.valid2);
        if (!valid) return;
        int t = rg==0 ? u.t0 : (rg==1 ? u.t1 : u.t2);
        const float* gx  = rg==0 ? u.gx0  : (rg==1 ? u.gx1  : u.gx2);
        const float* wxb = rg==0 ? u.wxb0 : (rg==1 ? u.wxb1 : u.wxb2);
        const float* whb = rg==0 ? u.whb0 : (rg==1 ? u.whb1 : u.whb2);
        int pbase = rg==0 ? 0 : (rg==1 ? 1 : 3);
        int np    = rg + 1;

        const float* gxr = gx + ((long long)b*TT + t)*G4;
        float g0 = gxr[n]        + wxb[n]        + whb[n];
        float g1 = gxr[DD+n]     + wxb[DD+n]     + whb[DD+n];
        float g2 = gxr[2*DD+n]   + wxb[2*DD+n]   + whb[2*DD+n];
        float g3 = gxr[3*DD+n]   + wxb[3*DD+n]   + whb[3*DD+n];
        const float* pp = u.part + (long long)pbase*BB*G4 + (long long)b*G4;
        for (int z = 0; z < np; z++, pp += (long long)BB*G4) {
            g0 += pp[n]; g1 += pp[DD+n]; g2 += pp[2*DD+n]; g3 += pp[3*DD+n];
        }
        float f  = sigm(g0);
        float i  = sigm(g1);
        float o  = sigm(g2);
        float cb = tanhf(g3);
        float ddv = (rg == 0) ? tanhf(u.dd0[((long long)b*TT + t)*DD + n])
                              : u.dd[(long long)(rg-1)*BD + idx];
        float* cp = u.c + (long long)rg*BD;
        float cv = f*cp[idx] + i*cb + ddv;
        cp[idx] = cv;
        float hv = o * tanhf(cv);
        long long hoff = (((long long)(t & 3)*LL) + rg)*BD + idx;
        u.h[hoff] = hv;
        __nv_bfloat16 bh = __float2bfloat16(hv);
        g_hbh[hoff] = bh;
        g_hbl[hoff] = __float2bfloat16(hv - __bfloat162float(bh));
    } else {
        if (!u.pvalid) return;
        float v = u.pb[n] + u.pp[idx] + u.pp[(long long)BB*OO + idx] + u.pp[2ll*BB*OO + idx];
        u.out[((long long)b*TT + u.tp)*OO + n] = v;
    }
}

// ---------------- weight image prep: transpose + bf16 hi/lo split ----------------
struct WImg { const float* src; int N; long long off; };
struct WTab { WImg im[12]; };

__global__ void wprep(WTab T)
{
    WImg im = T.im[blockIdx.z];
    int idx = blockIdx.x*256 + threadIdx.x;       // over N*64 8-elem units
    if (idx >= im.N*64) return;
    int n  = idx >> 6;
    int ku = idx & 63;
    __nv_bfloat16 hi[8], lo[8];
#pragma unroll
    for (int j = 0; j < 8; j++) {
        float w = im.src[(size_t)(ku*8 + j)*im.N + n];
        __nv_bfloat16 h = __float2bfloat16(w);
        hi[j] = h;
        lo[j] = __float2bfloat16(w - __bfloat162float(h));
    }
    size_t d = (size_t)im.off + (size_t)n*512 + (size_t)ku*8;
    *(uint4*)&g_wih[d] = *(uint4*)hi;
    *(uint4*)&g_wil[d] = *(uint4*)lo;
}

// ---------------- X -> bf16 hi/lo ----------------
__global__ void xconv(const float* __restrict__ X)
{
    long long i4 = ((long long)blockIdx.x*256 + threadIdx.x);
    const float4 v = *(const float4*)(X + i4*4);
    __nv_bfloat16 hi[4], lo[4];
    float xs[4] = {v.x, v.y, v.z, v.w};
#pragma unroll
    for (int j = 0; j < 4; j++) {
        hi[j] = __float2bfloat16(xs[j]);
        lo[j] = __float2bfloat16(xs[j] - __bfloat162float(hi[j]));
    }
    *(uint2*)&g_xbh[i4*4] = *(uint2*)hi;
    *(uint2*)&g_xbl[i4*4] = *(uint2*)lo;
}

// ---------------- layer-0 key scan ----------------
__global__ void scan_d0(const float* __restrict__ grx0, const float* __restrict__ keys,
                        float* __restrict__ d0all)
{
    int i = blockIdx.x*256 + threadIdx.x;
    int b = i >> 6, kk = i & 63;
    float d = keys[i];
    for (int t = 0; t < TT; t++) {
        float g = grx0[((long long)b*TT + t)*KK + kk];
        d *= 1.0f/(1.0f + expf(-g));
        d0all[((long long)b*TT + t)*KK + kk] = d;
    }
}

// ---------------- state init ----------------
__global__ void init_kernel(float* __restrict__ h, float* __restrict__ c,
                            float* __restrict__ d, const float* __restrict__ keys)
{
    const __nv_bfloat16 z16 = __float2bfloat16(0.0f);
    for (long long idx = (long long)blockIdx.x*256 + threadIdx.x;
         idx < 4ll*LL*BD; idx += (long long)gridDim.x*256) {
        h[idx] = 0.0f;
        g_hbh[idx] = z16;
        g_hbl[idx] = z16;
        if (idx < (long long)LL*BD)    c[idx] = 0.0f;
        if (idx < (long long)LL*BB*KK) d[idx] = keys[idx % (BB*KK)];
    }
}

// ---------------- host orchestration ----------------
static const long long IMG_OFF[12] = {
    0, 1048576, 2097152, 3145728, 4194304, 5242880,            // gate planes 0..5
    6291456, 6553600, 6815744,                                 // proj 0..2
    7077888, 8126464, 9175040                                  // gx 0..2
};

extern "C" void kernel_launch(void* const* d_in, const int* in_sizes, int n_in,
                              void* d_out, int out_size)
{
    const float* X    = (const float*)d_in[0];
    const float* keys = (const float*)d_in[1];

    const float *wx_w[LL], *wx_b[LL], *wh_w[LL], *wh_b[LL], *wr_w[LL], *wl_w[LL];
    if (in_sizes[4] == 512*2048) {
        for (int l = 0; l < LL; l++) {      // dict order
            int base = 2 + 6*l;
            wx_w[l] = (const float*)d_in[base+0];
            wx_b[l] = (const float*)d_in[base+1];
            wh_w[l] = (const float*)d_in[base+2];
            wh_b[l] = (const float*)d_in[base+3];
            wr_w[l] = (const float*)d_in[base+4];
            wl_w[l] = (const float*)d_in[base+5];
        }
    } else {
        for (int l = 0; l < LL; l++) {      // signature order
            wx_w[l] = (const float*)d_in[2 + 2*l];
            wx_b[l] = (const float*)d_in[3 + 2*l];
            wh_w[l] = (const float*)d_in[8 + 2*l];
            wh_b[l] = (const float*)d_in[9 + 2*l];
            wr_w[l] = (const float*)d_in[14 + l];
            wl_w[l] = (const float*)d_in[17 + l];
        }
    }
    const float* wd     = (const float*)d_in[20];
    const float* proj_w = (const float*)d_in[21];
    const float* proj_b = (const float*)d_in[22];
    float* out = (float*)d_out;

    float *p_gx, *p_Grx, *p_d0all, *p_dd0, *p_h, *p_c, *p_d, *p_dd, *p_part, *p_ppart;
    __nv_bfloat16 *p_wih, *p_wil, *p_xbh, *p_xbl, *p_hbh, *p_hbl;
    cudaGetSymbolAddress((void**)&p_gx,    g_gx);
    cudaGetSymbolAddress((void**)&p_Grx,   g_Grx);
    cudaGetSymbolAddress((void**)&p_d0all, g_d0all);
    cudaGetSymbolAddress((void**)&p_dd0,   g_dd0);
    cudaGetSymbolAddress((void**)&p_h,     g_h);
    cudaGetSymbolAddress((void**)&p_c,     g_c);
    cudaGetSymbolAddress((void**)&p_d,     g_d);
    cudaGetSymbolAddress((void**)&p_dd,    g_dd);
    cudaGetSymbolAddress((void**)&p_part,  g_part);
    cudaGetSymbolAddress((void**)&p_ppart, g_ppart);
    cudaGetSymbolAddress((void**)&p_wih,   g_wih);
    cudaGetSymbolAddress((void**)&p_wil,   g_wil);
    cudaGetSymbolAddress((void**)&p_xbh,   g_xbh);
    cudaGetSymbolAddress((void**)&p_xbl,   g_xbl);
    cudaGetSymbolAddress((void**)&p_hbh,   g_hbh);
    cudaGetSymbolAddress((void**)&p_hbl,   g_hbl);

    const int MSM = 2*STGB;   // 81920 B dynamic smem (double-buffered tiles)
    cudaFuncSetAttribute(mma_stage, cudaFuncAttributeMaxDynamicSharedMemorySize, MSM);

    auto hbh = [&](int l, int t) {
        int slot = (t < 0) ? 3 : (t & 3);
        return p_hbh + (((long long)slot*LL) + l)*BD;
    };
    auto hbl = [&](int l, int t) {
        int slot = (t < 0) ? 3 : (t & 3);
        return p_hbl + (((long long)slot*LL) + l)*BD;
    };

    // ---- prologue ----
    init_kernel<<<12288, 256>>>(p_h, p_c, p_d, keys);

    {
        WTab T{};
        T.im[0] = { wh_w[0], G4, IMG_OFF[0] };
        T.im[1] = { wh_w[1], G4, IMG_OFF[1] };
        T.im[2] = { wx_w[1] + (long long)CC*G4, G4, IMG_OFF[2] };
        T.im[3] = { wh_w[2], G4, IMG_OFF[3] };
        T.im[4] = { wx_w[2] + (long long)CC*G4, G4, IMG_OFF[4] };
        T.im[5] = { wx_w[2] + (long long)(CC+DD)*G4, G4, IMG_OFF[5] };
        for (int l = 0; l < LL; l++)
            T.im[6+l] = { proj_w + (long long)l*DD*OO, OO, IMG_OFF[6+l] };
        for (int l = 0; l < LL; l++)
            T.im[9+l] = { wx_w[l], G4, IMG_OFF[9+l] };
        dim3 g(512, 1, 12);
        wprep<<<g, 256>>>(T);
    }
    xconv<<<(BT*CC/4)/256, 256>>>(X);

    // Grx (scalar, N=64, z=3)
    {
        SStage SA{};
        for (int l = 0; l < LL; l++)
            SA.p[l] = { X, CC, wr_w[l], KK, p_Grx + (long long)l*BT*KK, KK, 512, 1, 0 };
        dim3 g(1, BT/64, 3);
        gemm_s<64,4,8><<<g, 128>>>(SA);
    }
    scan_d0<<<BB*KK/256, 256>>>(p_Grx, keys, p_d0all);
    {
        SStage SA{};
        SA.p[0] = { p_d0all, KK, wd, DD, p_dd0, DD, KK, 4, 0 };
        SA.p[1].kind = -1; SA.p[2].kind = -1;
        dim3 g(4, BT/64, 1);
        gemm_s<128,8,8><<<g, 128>>>(SA);
    }
    // Gx (tensor mma, z=3)
    {
        TStage SA{};
        for (int i = 0; i < 11; i++) SA.p[i].kind = -1;
        for (int l = 0; l < LL; l++)
            SA.p[l] = { p_xbh, p_xbl, p_wih + IMG_OFF[9+l], p_wil + IMG_OFF[9+l],
                        p_gx + (long long)l*BT*G4, G4, 16, 0 };
        dim3 g(16, BT/128, 3);
        mma_stage<<<g, 256, MSM>>>(SA);
    }

    // ---- skewed-pipeline serial phase ----
    for (int s = 0; s <= TT + 2; s++) {
        const int t0 = s, t1 = s - 1, t2 = s - 2, tp = s - 3;
        const bool v0 = (t0 >= 0 && t0 < TT);
        const bool v1 = (t1 >= 0 && t1 < TT);
        const bool v2 = (t2 >= 0 && t2 < TT);
        const bool vp = (tp >= 0 && tp < TT);

        TStage SA{};
        for (int i = 0; i < 11; i++) SA.p[i].kind = -1;

        auto setg = [&](int pi, int al, int at, int img, float* o, long long ldc, int xmax) {
            SA.p[pi] = { hbh(al, at), hbl(al, at),
                         p_wih + IMG_OFF[img], p_wil + IMG_OFF[img],
                         o, ldc, xmax, 0 };
        };
        if (v0)
            setg(0, 0, t0-1, 0, p_part + 0ll*BB*G4, G4, 16);
        if (v1) {
            setg(1, 1, t1-1, 1, p_part + 1ll*BB*G4, G4, 16);
            setg(2, 0, t1,   2, p_part + 2ll*BB*G4, G4, 16);
        }
        if (v2) {
            setg(3, 2, t2-1, 3, p_part + 3ll*BB*G4, G4, 16);
            setg(4, 0, t2,   4, p_part + 4ll*BB*G4, G4, 16);
            setg(5, 1, t2,   5, p_part + 5ll*BB*G4, G4, 16);
        }
        if (vp)
            for (int l = 0; l < LL; l++)
                setg(6+l, l, tp, 6+l, p_ppart + (long long)l*BB*OO, OO, 4);

        if (v1) {
            SA.p[9].kind = 1;
            K1A& a = SA.k1[0];
            a.hn = p_h + (long long)(t1 & 3)*LL*BD;
            a.hp = p_h + (long long)((t1-1) & 3)*LL*BD;
            a.grx = p_Grx + 1ll*BT*KK;
            a.wr = wr_w[1]; a.wl0 = wl_w[0]; a.wl1 = wl_w[1]; a.wd = wd;
            a.dst = p_d + 1ll*BB*KK; a.dd = p_dd;
            a.l = 1; a.t = t1;
        }
        if (v2) {
            SA.p[10].kind = 2;
            K1A& a = SA.k1[1];
            a.hn = p_h + (long long)(t2 & 3)*LL*BD;
            a.hp = p_h + (long long)((t2-1) & 3)*LL*BD;
            a.grx = p_Grx + 2ll*BT*KK;
            a.wr = wr_w[2]; a.wl0 = wl_w[0]; a.wl1 = wl_w[1]; a.wd = wd;
            a.dst = p_d + 2ll*BB*KK; a.dd = p_dd + BD;
            a.l = 2; a.t = t2;
        }

        dim3 gg(16, 4, 11);
        mma_stage<<<gg, 256, MSM>>>(SA);

        UpdA u{};
        u.valid0 = v0; u.valid1 = v1; u.valid2 = v2; u.pvalid = vp;
        u.t0 = t0; u.t1 = t1; u.t2 = t2; u.tp = tp;
        u.gx0 = p_gx + 0ll*BT*G4; u.gx1 = p_gx + 1ll*BT*G4; u.gx2 = p_gx + 2ll*BT*G4;
        u.wxb0 = wx_b[0]; u.wxb1 = wx_b[1]; u.wxb2 = wx_b[2];
        u.whb0 = wh_b[0]; u.whb1 = wh_b[1]; u.whb2 = wh_b[2];
        u.part = p_part; u.dd0 = p_dd0; u.dd = p_dd;
        u.h = p_h; u.c = p_c;
        u.pb = proj_b; u.pp = p_ppart; u.out = out;
        stage_update<<<4096, 256>>>(u);
    }
}

// round 13
// speedup vs baseline: 3.9836x; 1.4174x over previous
#include <cuda_runtime.h>
#include <cuda_fp16.h>
#include <math.h>
#include <stdint.h>

#define BB  512
#define TT  55
#define CC  512
#define DD  512
#define KK  64
#define LL  3
#define OO  512
#define BT  (BB*TT)      // 28160
#define BD  (BB*DD)      // 262144
#define G4  2048

// ---------------- device scratch ----------------
__device__ float g_gx[(size_t)LL*BT*G4];
__device__ float g_Grx[(size_t)LL*BT*KK];
__device__ float g_d0all[(size_t)BT*KK];
__device__ float g_dd0[(size_t)BT*DD];
__device__ float g_h[4*LL*BD];                    // fp32 h ring (k1 reads)
__device__ __half g_hbh[4*LL*BD];                 // fp16 hi ring
__device__ __half g_hbl[4*LL*BD];                 // fp16 lo ring
__device__ float g_c[LL*BD];
__device__ float g_d[LL*BB*KK];
__device__ float g_dd[2*BD];
__device__ float g_part[6*(size_t)BB*G4];
__device__ float g_ppart[3*(size_t)BB*OO];
__device__ __half g_xbh[(size_t)BT*CC];           // X fp16 hi
__device__ __half g_xbl[(size_t)BT*CC];
// pre-transposed fp16 weight images, [n][k=512] row-major (12 images, hi only)
#define WIMG_TOT 10223616
__device__ __half g_wih[WIMG_TOT];

__device__ __forceinline__ float sigm(float x) { return 1.0f/(1.0f+expf(-x)); }

// ---- mma.sync m16n8k16 fp16 inputs, fp32 accum (base-target PTX) ----
__device__ __forceinline__ void mma16816(float* d, const uint32_t* a, const uint32_t* b) {
    asm volatile("mma.sync.aligned.m16n8k16.row.col.f32.f16.f16.f32 "
        "{%0,%1,%2,%3}, {%4,%5,%6,%7}, {%8,%9}, {%0,%1,%2,%3};"
        : "+f"(d[0]), "+f"(d[1]), "+f"(d[2]), "+f"(d[3])
        : "r"(a[0]), "r"(a[1]), "r"(a[2]), "r"(a[3]), "r"(b[0]), "r"(b[1]));
}
__device__ __forceinline__ void ldsm_x4(uint32_t* r, uint32_t addr) {
    asm volatile("ldmatrix.sync.aligned.m8n8.x4.shared.b16 {%0,%1,%2,%3}, [%4];"
        : "=r"(r[0]), "=r"(r[1]), "=r"(r[2]), "=r"(r[3]) : "r"(addr));
}
__device__ __forceinline__ uint32_t smem_u32(const void* p) {
    uint32_t a;
    asm("{ .reg .u64 t; cvta.to.shared.u64 t, %1; cvt.u32.u64 %0, t; }" : "=r"(a) : "l"(p));
    return a;
}
__device__ __forceinline__ void cp16(uint32_t dst, const void* src) {
    asm volatile("cp.async.cg.shared.global [%0], [%1], 16;" :: "r"(dst), "l"(src));
}
__device__ __forceinline__ void cp_commit() {
    asm volatile("cp.async.commit_group;" ::: "memory");
}
template<int N> __device__ __forceinline__ void cp_wait() {
    asm volatile("cp.async.wait_group %0;" :: "n"(N) : "memory");
}

// ---------------- key-gate body (256 threads; 8 batches per block) ----------------
struct K1A {
    const float *hp, *hn, *grx, *wr, *wl0, *wl1, *wd;
    float *dst, *dd;
    int l, t;
};
__device__ void k1_body(const K1A& a, int bx)
{
    __shared__ float dn_s[8][KK];
    const int tid = threadIdx.x;        // 256
    const int r   = tid >> 5;           // 0..7
    const int q   = tid & 31;
    const int b   = bx*8 + r;

    const long long gro = ((long long)b*TT + a.t)*KK;
    float acc0 = a.grx[gro + q];
    float acc1 = a.grx[gro + q + 32];
    for (int j = 0; j < a.l; j++) {
        const float* hnj = a.hn + (size_t)j*BD + (size_t)b*DD;
        const float* hpj = a.hp + (size_t)j*BD + (size_t)b*DD;
        const float* wrp = a.wr + (size_t)(CC + j*DD)*KK;
        const float* wlp = (j == 0 ? a.wl0 : a.wl1);
        float u0 = 0.f, u1 = 0.f;
#pragma unroll 4
        for (int m = 0; m < DD; m++) {
            float hv = hnj[m], pv = hpj[m];
            acc0 = fmaf(hv, wrp[(size_t)m*KK + q],      acc0);
            acc1 = fmaf(hv, wrp[(size_t)m*KK + q + 32], acc1);
            u0   = fmaf(pv, wlp[(size_t)m*KK + q],      u0);
            u1   = fmaf(pv, wlp[(size_t)m*KK + q + 32], u1);
        }
        acc0 += u0 * (1.0f/3.0f);
        acc1 += u1 * (1.0f/3.0f);
    }
    float dn0 = sigm(acc0) * a.dst[b*KK + q];
    float dn1 = sigm(acc1) * a.dst[b*KK + q + 32];
    a.dst[b*KK + q]      = dn0;
    a.dst[b*KK + q + 32] = dn1;
    dn_s[r][q]      = dn0;
    dn_s[r][q + 32] = dn1;
    __syncthreads();

    for (int e = tid; e < 8*DD; e += 256) {
        int r2 = e >> 9;
        int n  = e & 511;
        int bb = bx*8 + r2;
        float s = 0.0f;
#pragma unroll
        for (int qq = 0; qq < KK; qq++)
            s = fmaf(dn_s[r2][qq], a.wd[(size_t)qq*DD + n], s);
        a.dd[(size_t)bb*DD + n] = tanhf(s);
    }
}

// ---------------- mma stage kernel: fp16 2-term (A split, B single) ----------------
// Tile M=128,N=128,K=512 (16 chunks of 32, double-buffered). A row-major fp16 hi/lo;
// B from pre-transposed [n][512] fp16 images. 8 warps (2x4), warp tile 64x32.
struct TPlane {
    const __half *Ah, *Al;          // [M][512]
    const __half *Bh;               // image base [Np][512]
    float* out; long long ldc;
    int xmax; int kind;             // 0 gemm, -1 idle, 1 -> k1[0], 2 -> k1[1]
};
struct TStage { TPlane p[11]; K1A k1[2]; };

#define SPB   80        // smem row pitch in BYTES (40 halves)
#define TILEB 10240     // one 128x32 tile (bytes) with pitch
#define STGB  30720     // 3 tiles per stage (Ah, Al, Bh)
#define NKC   16

__global__ void __launch_bounds__(256)
mma_stage(TStage SA)
{
    extern __shared__ __align__(16) char sm[];

    const TPlane pl = SA.p[blockIdx.z];
    if (pl.kind < 0) return;
    if (pl.kind > 0) {
        k1_body(SA.k1[pl.kind - 1], blockIdx.y * gridDim.x + blockIdx.x);
        return;
    }
    if ((int)blockIdx.x >= pl.xmax) return;

    const int tid = threadIdx.x;
    const int wid = tid >> 5, lid = tid & 31;
    const int wm = wid >> 2, wn = wid & 3;         // warp grid 2x4
    const int gid = lid >> 2, tig = lid & 3;
    const int row0 = blockIdx.y * 128;
    const int col0 = blockIdx.x * 128;
    const uint32_t smb = smem_u32(sm);

    const int cr0 = tid >> 2, csg = tid & 3;       // cp.async row/segment mapping
    const int cr1 = (tid + 256) >> 2;

    float d[4][4][4];
#pragma unroll
    for (int i = 0; i < 4; i++)
#pragma unroll
        for (int j = 0; j < 4; j++)
#pragma unroll
            for (int e = 0; e < 4; e++) d[i][j][e] = 0.0f;

    auto copy_tiles = [&](int kc, int s) {
        uint32_t sb = smb + s*STGB;
        const size_t ka = (size_t)kc*32 + csg*8;
#pragma unroll
        for (int it = 0; it < 2; it++) {
            int r = it ? cr1 : cr0;
            uint32_t doff = (uint32_t)r*SPB + csg*16;
            cp16(sb + doff,           pl.Ah + (size_t)(row0 + r)*512 + ka);
            cp16(sb + TILEB + doff,   pl.Al + (size_t)(row0 + r)*512 + ka);
            cp16(sb + 2*TILEB + doff, pl.Bh + (size_t)(col0 + r)*512 + ka);
        }
    };

    // ldmatrix lane-address components
    const uint32_t aRow = (uint32_t)(wm*64 + (lid & 15));
    const uint32_t aK   = (uint32_t)((lid >> 4) * 8);
    const uint32_t bN   = (uint32_t)(wn*32 + ((lid >> 4) & 1)*8 + (lid & 7));
    const uint32_t bK   = (uint32_t)(((lid >> 3) & 1) * 8);

    copy_tiles(0, 0); cp_commit();
    int buf = 0;
    for (int kc = 0; kc < NKC; kc++) {
        if (kc + 1 < NKC) { copy_tiles(kc + 1, buf ^ 1); cp_commit(); cp_wait<1>(); }
        else              { cp_wait<0>(); }
        __syncthreads();

        const uint32_t ah_b = smb + buf*STGB;
        const uint32_t al_b = ah_b + TILEB;
        const uint32_t bh_b = ah_b + 2*TILEB;

#pragma unroll
        for (int kkh = 0; kkh < 32; kkh += 16) {
            uint32_t bh[4][2];
#pragma unroll
            for (int blk = 0; blk < 2; blk++) {
                uint32_t off = (bN + blk*16)*SPB + (bK + kkh)*2;
                uint32_t t[4];
                ldsm_x4(t, bh_b + off);
                bh[2*blk][0] = t[0]; bh[2*blk][1] = t[1];
                bh[2*blk+1][0] = t[2]; bh[2*blk+1][1] = t[3];
            }
#pragma unroll
            for (int i = 0; i < 4; i++) {
                uint32_t off = (aRow + i*16)*SPB + (aK + kkh)*2;
                uint32_t ah[4], al[4];
                ldsm_x4(ah, ah_b + off);
                ldsm_x4(al, al_b + off);
#pragma unroll
                for (int j = 0; j < 4; j++) {
                    mma16816(d[i][j], ah, bh[j]);
                    mma16816(d[i][j], al, bh[j]);
                }
            }
        }
        __syncthreads();
        buf ^= 1;
    }

#pragma unroll
    for (int i = 0; i < 4; i++) {
        long long r = row0 + wm*64 + i*16 + gid;
#pragma unroll
        for (int j = 0; j < 4; j++) {
            long long cn = col0 + wn*32 + j*8 + tig*2;
            *(float2*)&pl.out[r*pl.ldc + cn]       = make_float2(d[i][j][0], d[i][j][1]);
            *(float2*)&pl.out[(r+8)*pl.ldc + cn]   = make_float2(d[i][j][2], d[i][j][3]);
        }
    }
}

// ---------------- scalar segmented SGEMM (prologue Grx / dd0 only) ----------------
__device__ __forceinline__ void fma2(unsigned long long &d, unsigned long long a, unsigned long long b){
    asm("fma.rn.f32x2 %0, %1, %2, %0;" : "+l"(d) : "l"(a), "l"(b));
}
struct SPlane { const float* A; long long lda; const float* Bw; long long ldb;
                float* out; long long ldc; int K; int xmax; int kind; };
struct SStage { SPlane p[3]; };

template<int BN, int TM, int TN>
__global__ void __launch_bounds__((BN/TN)*(64/TM))
gemm_s(SStage SA)
{
    constexpr int BM = 64, BK = 16;
    constexpr int TX = BN/TN, TY = BM/TM, NT = TX*TY;
    constexpr int AW = 2*BM + 8;
    __shared__ __align__(16) float a_s[BK][AW];
    __shared__ __align__(16) float b_s[BK][BN];

    const SPlane pl = SA.p[blockIdx.z];
    if (pl.kind < 0) return;
    if ((int)blockIdx.x >= pl.xmax) return;

    const int tid  = threadIdx.x;
    const int tx   = tid % TX;
    const int ty   = tid / TX;
    const int row0 = blockIdx.y * BM;
    const int col0 = blockIdx.x * BN;

    unsigned long long acc[TM][TN/2];
#pragma unroll
    for (int i = 0; i < TM; i++)
#pragma unroll
        for (int j = 0; j < TN/2; j++) acc[i][j] = 0ull;

    for (int k0 = 0; k0 < pl.K; k0 += BK) {
#pragma unroll
        for (int e = tid; e < BM*BK/4; e += NT) {
            int r  = e >> 2;
            int kq = (e & 3) << 2;
            float4 v = *(const float4*)(pl.A + (long long)(row0 + r)*pl.lda + k0 + kq);
            *(float2*)&a_s[kq+0][2*r] = make_float2(v.x, v.x);
            *(float2*)&a_s[kq+1][2*r] = make_float2(v.y, v.y);
            *(float2*)&a_s[kq+2][2*r] = make_float2(v.z, v.z);
            *(float2*)&a_s[kq+3][2*r] = make_float2(v.w, v.w);
        }
#pragma unroll
        for (int e = tid; e < BK*BN/4; e += NT) {
            int kk = e / (BN/4);
            int n4 = (e % (BN/4)) * 4;
            *(float4*)&b_s[kk][n4] =
                *(const float4*)(pl.Bw + (long long)(k0+kk)*pl.ldb + col0 + n4);
        }
        __syncthreads();
#pragma unroll
        for (int kk = 0; kk < BK; kk++) {
            unsigned long long aa[TM], bq[TN/2];
            const ulonglong2* ap = (const ulonglong2*)&a_s[kk][2*(ty*TM)];
            const ulonglong2* bp = (const ulonglong2*)&b_s[kk][tx*TN];
#pragma unroll
            for (int i = 0; i < TM/2; i++) { ulonglong2 u = ap[i]; aa[2*i] = u.x; aa[2*i+1] = u.y; }
#pragma unroll
            for (int j = 0; j < TN/4; j++) { ulonglong2 v = bp[j]; bq[2*j] = v.x; bq[2*j+1] = v.y; }
#pragma unroll
            for (int i = 0; i < TM; i++)
#pragma unroll
                for (int j = 0; j < TN/2; j++)
                    fma2(acc[i][j], aa[i], bq[j]);
        }
        __syncthreads();
    }
#pragma unroll
    for (int i = 0; i < TM; i++) {
        long long r = row0 + ty*TM + i;
        float* orow = pl.out + r*pl.ldc + col0 + tx*TN;
#pragma unroll
        for (int j = 0; j < TN/2; j++)
            *(unsigned long long*)&orow[2*j] = acc[i][j];
    }
}

// ---------------- combined stage update (+ fp16 hi/lo h write) ----------------
struct UpdA {
    int valid0, valid1, valid2, pvalid;
    int t0, t1, t2, tp;
    const float *gx0, *gx1, *gx2;
    const float *wxb0, *wxb1, *wxb2, *whb0, *whb1, *whb2;
    const float *part, *dd0, *dd;
    float *h, *c;
    const float *pb; const float *pp; float *out;
};

__global__ void stage_update(UpdA u)
{
    const int rg = blockIdx.x >> 10;
    const long long idx = ((long long)(blockIdx.x & 1023))*256 + threadIdx.x;
    const int b = (int)(idx >> 9);
    const int n = (int)(idx & 511);

    if (rg < 3) {
        int valid = rg==0 ? u.valid0 : (rg==1 ? u.valid1 : u.valid2);
        if (!valid) return;
        int t = rg==0 ? u.t0 : (rg==1 ? u.t1 : u.t2);
        const float* gx  = rg==0 ? u.gx0  : (rg==1 ? u.gx1  : u.gx2);
        const float* wxb = rg==0 ? u.wxb0 : (rg==1 ? u.wxb1 : u.wxb2);
        const float* whb = rg==0 ? u.whb0 : (rg==1 ? u.whb1 : u.whb2);
        int pbase = rg==0 ? 0 : (rg==1 ? 1 : 3);
        int np    = rg + 1;

        const float* gxr = gx + ((long long)b*TT + t)*G4;
        float g0 = gxr[n]        + wxb[n]        + whb[n];
        float g1 = gxr[DD+n]     + wxb[DD+n]     + whb[DD+n];
        float g2 = gxr[2*DD+n]   + wxb[2*DD+n]   + whb[2*DD+n];
        float g3 = gxr[3*DD+n]   + wxb[3*DD+n]   + whb[3*DD+n];
        const float* pp = u.part + (long long)pbase*BB*G4 + (long long)b*G4;
        for (int z = 0; z < np; z++, pp += (long long)BB*G4) {
            g0 += pp[n]; g1 += pp[DD+n]; g2 += pp[2*DD+n]; g3 += pp[3*DD+n];
        }
        float f  = sigm(g0);
        float i  = sigm(g1);
        float o  = sigm(g2);
        float cb = tanhf(g3);
        float ddv = (rg == 0) ? tanhf(u.dd0[((long long)b*TT + t)*DD + n])
                              : u.dd[(long long)(rg-1)*BD + idx];
        float* cp = u.c + (long long)rg*BD;
        float cv = f*cp[idx] + i*cb + ddv;
        cp[idx] = cv;
        float hv = o * tanhf(cv);
        long long hoff = (((long long)(t & 3)*LL) + rg)*BD + idx;
        u.h[hoff] = hv;
        __half hh = __float2half_rn(hv);
        g_hbh[hoff] = hh;
        g_hbl[hoff] = __float2half_rn(hv - __half2float(hh));
    } else {
        if (!u.pvalid) return;
        float v = u.pb[n] + u.pp[idx] + u.pp[(long long)BB*OO + idx] + u.pp[2ll*BB*OO + idx];
        u.out[((long long)b*TT + u.tp)*OO + n] = v;
    }
}

// ---------------- weight image prep: transpose + fp16 (hi only) ----------------
struct WImg { const float* src; int N; long long off; };
struct WTab { WImg im[12]; };

__global__ void wprep(WTab T)
{
    WImg im = T.im[blockIdx.z];
    int idx = blockIdx.x*256 + threadIdx.x;       // over N*64 8-elem units
    if (idx >= im.N*64) return;
    int n  = idx >> 6;
    int ku = idx & 63;
    __half hi[8];
#pragma unroll
    for (int j = 0; j < 8; j++)
        hi[j] = __float2half_rn(im.src[(size_t)(ku*8 + j)*im.N + n]);
    size_t d = (size_t)im.off + (size_t)n*512 + (size_t)ku*8;
    *(uint4*)&g_wih[d] = *(uint4*)hi;
}

// ---------------- X -> fp16 hi/lo ----------------
__global__ void xconv(const float* __restrict__ X)
{
    long long i4 = ((long long)blockIdx.x*256 + threadIdx.x);
    const float4 v = *(const float4*)(X + i4*4);
    __half hi[4], lo[4];
    float xs[4] = {v.x, v.y, v.z, v.w};
#pragma unroll
    for (int j = 0; j < 4; j++) {
        hi[j] = __float2half_rn(xs[j]);
        lo[j] = __float2half_rn(xs[j] - __half2float(hi[j]));
    }
    *(uint2*)&g_xbh[i4*4] = *(uint2*)hi;
    *(uint2*)&g_xbl[i4*4] = *(uint2*)lo;
}

// ---------------- layer-0 key scan ----------------
__global__ void scan_d0(const float* __restrict__ grx0, const float* __restrict__ keys,
                        float* __restrict__ d0all)
{
    int i = blockIdx.x*256 + threadIdx.x;
    int b = i >> 6, kk = i & 63;
    float d = keys[i];
    for (int t = 0; t < TT; t++) {
        float g = grx0[((long long)b*TT + t)*KK + kk];
        d *= 1.0f/(1.0f + expf(-g));
        d0all[((long long)b*TT + t)*KK + kk] = d;
    }
}

// ---------------- state init ----------------
__global__ void init_kernel(float* __restrict__ h, float* __restrict__ c,
                            float* __restrict__ d, const float* __restrict__ keys)
{
    const __half z16 = __float2half_rn(0.0f);
    for (long long idx = (long long)blockIdx.x*256 + threadIdx.x;
         idx < 4ll*LL*BD; idx += (long long)gridDim.x*256) {
        h[idx] = 0.0f;
        g_hbh[idx] = z16;
        g_hbl[idx] = z16;
        if (idx < (long long)LL*BD)    c[idx] = 0.0f;
        if (idx < (long long)LL*BB*KK) d[idx] = keys[idx % (BB*KK)];
    }
}

// ---------------- host orchestration ----------------
static const long long IMG_OFF[12] = {
    0, 1048576, 2097152, 3145728, 4194304, 5242880,            // gate planes 0..5
    6291456, 6553600, 6815744,                                 // proj 0..2
    7077888, 8126464, 9175040                                  // gx 0..2
};

extern "C" void kernel_launch(void* const* d_in, const int* in_sizes, int n_in,
                              void* d_out, int out_size)
{
    const float* X    = (const float*)d_in[0];
    const float* keys = (const float*)d_in[1];

    const float *wx_w[LL], *wx_b[LL], *wh_w[LL], *wh_b[LL], *wr_w[LL], *wl_w[LL];
    if (in_sizes[4] == 512*2048) {
        for (int l = 0; l < LL; l++) {      // dict order
            int base = 2 + 6*l;
            wx_w[l] = (const float*)d_in[base+0];
            wx_b[l] = (const float*)d_in[base+1];
            wh_w[l] = (const float*)d_in[base+2];
            wh_b[l] = (const float*)d_in[base+3];
            wr_w[l] = (const float*)d_in[base+4];
            wl_w[l] = (const float*)d_in[base+5];
        }
    } else {
        for (int l = 0; l < LL; l++) {      // signature order
            wx_w[l] = (const float*)d_in[2 + 2*l];
            wx_b[l] = (const float*)d_in[3 + 2*l];
            wh_w[l] = (const float*)d_in[8 + 2*l];
            wh_b[l] = (const float*)d_in[9 + 2*l];
            wr_w[l] = (const float*)d_in[14 + l];
            wl_w[l] = (const float*)d_in[17 + l];
        }
    }
    const float* wd     = (const float*)d_in[20];
    const float* proj_w = (const float*)d_in[21];
    const float* proj_b = (const float*)d_in[22];
    float* out = (float*)d_out;

    float *p_gx, *p_Grx, *p_d0all, *p_dd0, *p_h, *p_c, *p_d, *p_dd, *p_part, *p_ppart;
    __half *p_wih, *p_xbh, *p_xbl, *p_hbh, *p_hbl;
    cudaGetSymbolAddress((void**)&p_gx,    g_gx);
    cudaGetSymbolAddress((void**)&p_Grx,   g_Grx);
    cudaGetSymbolAddress((void**)&p_d0all, g_d0all);
    cudaGetSymbolAddress((void**)&p_dd0,   g_dd0);
    cudaGetSymbolAddress((void**)&p_h,     g_h);
    cudaGetSymbolAddress((void**)&p_c,     g_c);
    cudaGetSymbolAddress((void**)&p_d,     g_d);
    cudaGetSymbolAddress((void**)&p_dd,    g_dd);
    cudaGetSymbolAddress((void**)&p_part,  g_part);
    cudaGetSymbolAddress((void**)&p_ppart, g_ppart);
    cudaGetSymbolAddress((void**)&p_wih,   g_wih);
    cudaGetSymbolAddress((void**)&p_xbh,   g_xbh);
    cudaGetSymbolAddress((void**)&p_xbl,   g_xbl);
    cudaGetSymbolAddress((void**)&p_hbh,   g_hbh);
    cudaGetSymbolAddress((void**)&p_hbl,   g_hbl);

    const int MSM = 2*STGB;   // 61440 B dynamic smem
    cudaFuncSetAttribute(mma_stage, cudaFuncAttributeMaxDynamicSharedMemorySize, MSM);

    auto hbh = [&](int l, int t) {
        int slot = (t < 0) ? 3 : (t & 3);
        return p_hbh + (((long long)slot*LL) + l)*BD;
    };
    auto hbl = [&](int l, int t) {
        int slot = (t < 0) ? 3 : (t & 3);
        return p_hbl + (((long long)slot*LL) + l)*BD;
    };

    // ---- prologue (mma Gx first so ncu's sample lands on mma_stage) ----
    init_kernel<<<12288, 256>>>(p_h, p_c, p_d, keys);

    {
        WTab T{};
        T.im[0] = { wh_w[0], G4, IMG_OFF[0] };
        T.im[1] = { wh_w[1], G4, IMG_OFF[1] };
        T.im[2] = { wx_w[1] + (long long)CC*G4, G4, IMG_OFF[2] };
        T.im[3] = { wh_w[2], G4, IMG_OFF[3] };
        T.im[4] = { wx_w[2] + (long long)CC*G4, G4, IMG_OFF[4] };
        T.im[5] = { wx_w[2] + (long long)(CC+DD)*G4, G4, IMG_OFF[5] };
        for (int l = 0; l < LL; l++)
            T.im[6+l] = { proj_w + (long long)l*DD*OO, OO, IMG_OFF[6+l] };
        for (int l = 0; l < LL; l++)
            T.im[9+l] = { wx_w[l], G4, IMG_OFF[9+l] };
        dim3 g(512, 1, 12);
        wprep<<<g, 256>>>(T);
    }
    xconv<<<(BT*CC/4)/256, 256>>>(X);

    // Gx (tensor mma, z=3)
    {
        TStage SA{};
        for (int i = 0; i < 11; i++) SA.p[i].kind = -1;
        for (int l = 0; l < LL; l++)
            SA.p[l] = { p_xbh, p_xbl, p_wih + IMG_OFF[9+l],
                        p_gx + (long long)l*BT*G4, G4, 16, 0 };
        dim3 g(16, BT/128, 3);
        mma_stage<<<g, 256, MSM>>>(SA);
    }

    // Grx (scalar, N=64, z=3)
    {
        SStage SA{};
        for (int l = 0; l < LL; l++)
            SA.p[l] = { X, CC, wr_w[l], KK, p_Grx + (long long)l*BT*KK, KK, 512, 1, 0 };
        dim3 g(1, BT/64, 3);
        gemm_s<64,4,8><<<g, 128>>>(SA);
    }
    scan_d0<<<BB*KK/256, 256>>>(p_Grx, keys, p_d0all);
    {
        SStage SA{};
        SA.p[0] = { p_d0all, KK, wd, DD, p_dd0, DD, KK, 4, 0 };
        SA.p[1].kind = -1; SA.p[2].kind = -1;
        dim3 g(4, BT/64, 1);
        gemm_s<128,8,8><<<g, 128>>>(SA);
    }

    // ---- skewed-pipeline serial phase ----
    for (int s = 0; s <= TT + 2; s++) {
        const int t0 = s, t1 = s - 1, t2 = s - 2, tp = s - 3;
        const bool v0 = (t0 >= 0 && t0 < TT);
        const bool v1 = (t1 >= 0 && t1 < TT);
        const bool v2 = (t2 >= 0 && t2 < TT);
        const bool vp = (tp >= 0 && tp < TT);

        TStage SA{};
        for (int i = 0; i < 11; i++) SA.p[i].kind = -1;

        auto setg = [&](int pi, int al, int at, int img, float* o, long long ldc, int xmax) {
            SA.p[pi] = { hbh(al, at), hbl(al, at),
                         p_wih + IMG_OFF[img],
                         o, ldc, xmax, 0 };
        };
        if (v0)
            setg(0, 0, t0-1, 0, p_part + 0ll*BB*G4, G4, 16);
        if (v1) {
            setg(1, 1, t1-1, 1, p_part + 1ll*BB*G4, G4, 16);
            setg(2, 0, t1,   2, p_part + 2ll*BB*G4, G4, 16);
        }
        if (v2) {
            setg(3, 2, t2-1, 3, p_part + 3ll*BB*G4, G4, 16);
            setg(4, 0, t2,   4, p_part + 4ll*BB*G4, G4, 16);
            setg(5, 1, t2,   5, p_part + 5ll*BB*G4, G4, 16);
        }
        if (vp)
            for (int l = 0; l < LL; l++)
                setg(6+l, l, tp, 6+l, p_ppart + (long long)l*BB*OO, OO, 4);

        if (v1) {
            SA.p[9].kind = 1;
            K1A& a = SA.k1[0];
            a.hn = p_h + (long long)(t1 & 3)*LL*BD;
            a.hp = p_h + (long long)((t1-1) & 3)*LL*BD;
            a.grx = p_Grx + 1ll*BT*KK;
            a.wr = wr_w[1]; a.wl0 = wl_w[0]; a.wl1 = wl_w[1]; a.wd = wd;
            a.dst = p_d + 1ll*BB*KK; a.dd = p_dd;
            a.l = 1; a.t = t1;
        }
        if (v2) {
            SA.p[10].kind = 2;
            K1A& a = SA.k1[1];
            a.hn = p_h + (long long)(t2 & 3)*LL*BD;
            a.hp = p_h + (long long)((t2-1) & 3)*LL*BD;
            a.grx = p_Grx + 2ll*BT*KK;
            a.wr = wr_w[2]; a.wl0 = wl_w[0]; a.wl1 = wl_w[1]; a.wd = wd;
            a.dst = p_d + 2ll*BB*KK; a.dd = p_dd + BD;
            a.l = 2; a.t = t2;
        }

        dim3 gg(16, 4, 11);
        mma_stage<<<gg, 256, MSM>>>(SA);

        UpdA u{};
        u.valid0 = v0; u.valid1 = v1; u.valid2 = v2; u.pvalid = vp;
        u.t0 = t0; u.t1 = t1; u.t2 = t2; u.tp = tp;
        u.gx0 = p_gx + 0ll*BT*G4; u.gx1 = p_gx + 1ll*BT*G4; u.gx2 = p_gx + 2ll*BT*G4;
        u.wxb0 = wx_b[0]; u.wxb1 = wx_b[1]; u.wxb2 = wx_b[2];
        u.whb0 = wh_b[0]; u.whb1 = wh_b[1]; u.whb2 = wh_b[2];
        u.part = p_part; u.dd0 = p_dd0; u.dd = p_dd;
        u.h = p_h; u.c = p_c;
        u.pb = proj_b; u.pp = p_ppart; u.out = out;
        stage_update<<<4096, 256>>>(u);
    }
}